// round 3
// baseline (speedup 1.0000x reference)
#include <cuda_runtime.h>

#define NN   50000
#define EE   400000
#define EMB  32
#define NREL 8
#define NLAY 5
#define WPB  8            // warps per block (256 threads)

// ---------------- scratch (static device globals; no allocations) ----------
__device__ float g_W2t[32 * 1024];               // W2 transposed to [i][(k,o)]
__device__ float g_h[2][NN * EMB];
__device__ float g_disc[NN * EMB];
__device__ float g_agg[NN * EMB];
__device__ float g_invdeg[NN];
__device__ float g_invrel[NREL][NN];
__device__ int   g_counter;
// CSR by source (segments in arbitrary order)
__device__ int   g_outdeg[NN];
__device__ int   g_cursor[NN];
__device__ int   g_rowptr[NN];
__device__ int   g_ceid[EE];
__device__ int   g_cdst[EE];
__device__ int   g_crel[EE];
__device__ float g_cwn[EE];                      // invdeg[dst]
__device__ float g_cwr[EE];                      // invrel[r][dst]
__device__ float g_chid[(size_t)EE * 32];        // per-edge hidden (layer-invariant)

// ---------------- zero / counts ---------------------------------------------
__global__ void zero_counts_kernel() {
    int i = blockIdx.x * blockDim.x + threadIdx.x;
    if (i == 0) g_counter = 0;
    if (i < NN) { g_invdeg[i] = 0.f; g_outdeg[i] = 0; }
    if (i < NN * NREL) ((float*)g_invrel)[i] = 0.f;
}

__global__ void zero_accum_kernel() {
    int i = blockIdx.x * blockDim.x + threadIdx.x;
    if (i < NN * EMB) { g_disc[i] = 0.f; g_agg[i] = 0.f; }
}

__global__ void count_kernel(const int* __restrict__ src,
                             const int* __restrict__ dst,
                             const int* __restrict__ etype) {
    int e = blockIdx.x * blockDim.x + threadIdx.x;
    if (e >= EE) return;
    int d = dst[e], r = etype[e];
    atomicAdd(&g_invdeg[d], 1.f);
    atomicAdd(&g_invrel[r][d], 1.f);
    atomicAdd(&g_outdeg[src[e]], 1);
}

__global__ void invert_kernel() {
    int i = blockIdx.x * blockDim.x + threadIdx.x;
    if (i < NN) g_invdeg[i] = 1.f / fmaxf(g_invdeg[i], 1.f);
    if (i < NN * NREL) {
        float v = ((float*)g_invrel)[i];
        ((float*)g_invrel)[i] = 1.f / fmaxf(v, 1.f);
    }
}

// ---------------- rowptr via atomic segment assignment (order-free) ---------
__global__ void assign_kernel() {
    int i = blockIdx.x * blockDim.x + threadIdx.x;
    if (i >= NN) return;
    g_rowptr[i] = atomicAdd(&g_counter, g_outdeg[i]);
    g_cursor[i] = 0;
}

// ---------------- fill CSR ---------------------------------------------------
__global__ void fill_kernel(const int* __restrict__ src,
                            const int* __restrict__ dst,
                            const int* __restrict__ etype) {
    int e = blockIdx.x * blockDim.x + threadIdx.x;
    if (e >= EE) return;
    int s = src[e];
    int pos = g_rowptr[s] + atomicAdd(&g_cursor[s], 1);
    g_ceid[pos] = e;
    g_cdst[pos] = dst[e];
    g_crel[pos] = etype[e];
}

// ---------------- per-edge hidden (layer-invariant) + scales ----------------
__global__ __launch_bounds__(WPB * 32) void hid_kernel(
    const int* __restrict__ etype, const float* __restrict__ edist,
    const float* __restrict__ W1, const float* __restrict__ b1) {
    int warp = threadIdx.x >> 5, lane = threadIdx.x & 31;
    int pos = blockIdx.x * WPB + warp;
    if (pos >= EE) return;
    int e = g_ceid[pos];
    int r = etype[e];
    float dd = edist[e];
    float h = fmaxf(dd * W1[lane] + W1[(1 + r) * 32 + lane] + b1[lane], 0.f);
    g_chid[(size_t)pos * 32 + lane] = h;
    if (lane == 0) {
        int dn = g_cdst[pos];
        g_cwn[pos] = g_invdeg[dn];
        g_cwr[pos] = g_invrel[r][dn];
    }
}

// ---------------- transpose W2: g_W2t[i][(k,o)] = W2[k][i*32+o] -------------
__global__ void w2t_kernel(const float* __restrict__ W2) {
    int idx = blockIdx.x * blockDim.x + threadIdx.x;
    if (idx >= 32 * 1024) return;
    int i = idx >> 10, rest = idx & 1023;   // rest = k*32+o
    int k = rest >> 5, o = rest & 31;
    g_W2t[idx] = W2[k * 1024 + i * 32 + o];
}

// ---------------- h0 = relu(x @ fc_W + fc_b) --------------------------------
__global__ __launch_bounds__(WPB * 32) void fc_kernel(
    const float* __restrict__ x, const float* __restrict__ W,
    const float* __restrict__ b) {
    int warp = threadIdx.x >> 5, lane = threadIdx.x & 31;
    int n = blockIdx.x * WPB + warp;
    if (n >= NN) return;
    float xv = x[n * 32 + lane];
    float acc = b[lane];
#pragma unroll
    for (int k = 0; k < 32; k++)
        acc = fmaf(__shfl_sync(0xffffffffu, xv, k), W[k * 32 + lane], acc);
    g_h[0][n * 32 + lane] = fmaxf(acc, 0.f);
}

// ---------------- fused G-compute + edge scatter ----------------------------
// Block = 8 source nodes (1 warp each). Dynamic smem layout (floats):
//   sWr  [0,8192)      rW for this layer [R][32][32]
//   sb2  [8192,9216)   b2 as [i][o]
//   sXr  [9216,11264)  per-warp per-relation messages [8][8][32]
//   sW   [11264,19456) W2t staging chunk 32x256 (reused 4x)
#define SM_WR  0
#define SM_B2  8192
#define SM_XR  9216
#define SM_W   11264
#define SM_FLOATS 19456

__global__ __launch_bounds__(256) void fused_kernel(
    int p, const float* __restrict__ rW, const float* __restrict__ b2) {
    extern __shared__ float sm[];
    int t = threadIdx.x;
    int warp = t >> 5, lane = t & 31;
    int n = blockIdx.x * WPB + warp;
    bool valid = (n < NN);

    // load rW (32KB) + b2 (4KB)
#pragma unroll
    for (int j = 0; j < 8; j++)
        *(float4*)&sm[SM_WR + (t + j * 256) * 4] = *(const float4*)&rW[(t + j * 256) * 4];
    *(float4*)&sm[SM_B2 + t * 4] = *(const float4*)&b2[t * 4];
    __syncthreads();

    float hs = valid ? g_h[p][(size_t)n * 32 + lane] : 0.f;

    // RGCN per-relation source messages + NNConv bias row
    float B = 0.f;
    {
        float xr[NREL];
#pragma unroll
        for (int r = 0; r < NREL; r++) xr[r] = 0.f;
#pragma unroll
        for (int i = 0; i < 32; i++) {
            float hv = __shfl_sync(0xffffffffu, hs, i);
            B = fmaf(hv, sm[SM_B2 + i * 32 + lane], B);
#pragma unroll
            for (int r = 0; r < NREL; r++)
                xr[r] = fmaf(hv, sm[SM_WR + r * 1024 + i * 32 + lane], xr[r]);
        }
#pragma unroll
        for (int r = 0; r < NREL; r++)
            sm[SM_XR + warp * 256 + r * 32 + lane] = xr[r];
    }

    // Greg[k] = G[n][k][lane] = sum_i h[n][i] * W2t[i][k*32+lane]
    float Greg[32];
#pragma unroll
    for (int k = 0; k < 32; k++) Greg[k] = 0.f;
#pragma unroll
    for (int q = 0; q < 4; q++) {
        __syncthreads();
        // stage W2t rows i=0..31, flat cols [q*256,(q+1)*256): 8192 floats
#pragma unroll
        for (int j = 0; j < 8; j++) {
            int id4 = t + j * 256;          // float4 index within chunk
            int i = id4 >> 6;               // 64 float4 per row of 256
            int c = (id4 & 63) * 4;
            *(float4*)&sm[SM_W + i * 256 + c] =
                *(const float4*)&g_W2t[i * 1024 + q * 256 + c];
        }
        __syncthreads();
#pragma unroll
        for (int i = 0; i < 32; i++) {
            float hv = __shfl_sync(0xffffffffu, hs, i);
#pragma unroll
            for (int j = 0; j < 8; j++)
                Greg[q * 8 + j] = fmaf(hv, sm[SM_W + i * 256 + 32 * j + lane],
                                       Greg[q * 8 + j]);
        }
    }

    if (!valid) return;

    int beg = g_rowptr[n];
    int end = beg + g_outdeg[n];
    for (int pos = beg; pos < end; pos++) {
        int   d  = g_cdst[pos];
        int   r  = g_crel[pos];
        float wn = g_cwn[pos];
        float wr = g_cwr[pos];
        float hid = g_chid[(size_t)pos * 32 + lane];

        float m0 = 0.f, m1 = 0.f, m2 = 0.f, m3 = 0.f;
#pragma unroll
        for (int k = 0; k < 32; k += 4) {
            m0 = fmaf(__shfl_sync(0xffffffffu, hid, k + 0), Greg[k + 0], m0);
            m1 = fmaf(__shfl_sync(0xffffffffu, hid, k + 1), Greg[k + 1], m1);
            m2 = fmaf(__shfl_sync(0xffffffffu, hid, k + 2), Greg[k + 2], m2);
            m3 = fmaf(__shfl_sync(0xffffffffu, hid, k + 3), Greg[k + 3], m3);
        }
        float m  = (m0 + m1) + (m2 + m3) + B;
        float rm = sm[SM_XR + warp * 256 + r * 32 + lane];

        atomicAdd(&g_disc[(size_t)d * 32 + lane], rm * wr);
        atomicAdd(&g_agg[(size_t)d * 32 + lane],  m * wn);
    }
}

// ---------------- combine: root transforms + residual + reset accum ---------
__global__ __launch_bounds__(WPB * 32) void combine_kernel(
    int p, const float* __restrict__ rroot, const float* __restrict__ rbias,
    const float* __restrict__ nroot, const float* __restrict__ nbias,
    float* __restrict__ out_final) {
    int warp = threadIdx.x >> 5, lane = threadIdx.x & 31;
    int n = blockIdx.x * WPB + warp;
    if (n >= NN) return;
    size_t idx = (size_t)n * 32 + lane;
    float hv = g_h[p][idx];
    float accD = rbias[lane];
    float accN = nbias[lane];
#pragma unroll
    for (int k = 0; k < 32; k++) {
        float v = __shfl_sync(0xffffffffu, hv, k);
        accD = fmaf(v, rroot[k * 32 + lane], accD);
        accN = fmaf(v, nroot[k * 32 + lane], accN);
    }
    float v = hv + fmaxf(accD + g_disc[idx], 0.f)
                 + fmaxf(accN + g_agg[idx], 0.f);
    g_disc[idx] = 0.f;
    g_agg[idx]  = 0.f;
    if (out_final) out_final[idx] = v;
    else           g_h[p ^ 1][idx] = v;
}

// ---------------- host launch ------------------------------------------------
extern "C" void kernel_launch(void* const* d_in, const int* in_sizes, int n_in,
                              void* d_out, int out_size) {
    const float* x     = (const float*)d_in[0];
    const int*   eidx  = (const int*)  d_in[1];   // [2,E]: src then dst
    const int*   etype = (const int*)  d_in[2];
    const float* edist = (const float*)d_in[3];
    const float* fcW   = (const float*)d_in[4];
    const float* fcb   = (const float*)d_in[5];
    const float* rW    = (const float*)d_in[6];   // [L,R,32,32]
    const float* rroot = (const float*)d_in[7];   // [L,32,32]
    const float* rbias = (const float*)d_in[8];   // [L,32]
    const float* W1    = (const float*)d_in[9];   // [9,32]
    const float* b1    = (const float*)d_in[10];  // [32]
    const float* W2    = (const float*)d_in[11];  // [32,1024]
    const float* b2    = (const float*)d_in[12];  // [1024]
    const float* nroot = (const float*)d_in[13];  // [L,32,32]
    const float* nbias = (const float*)d_in[14];  // [L,32]
    float* out = (float*)d_out;

    const int* srcp = eidx;
    const int* dstp = eidx + EE;

    cudaFuncSetAttribute(fused_kernel,
                         cudaFuncAttributeMaxDynamicSharedMemorySize,
                         SM_FLOATS * 4);

    int cnt = NN * NREL;
    zero_counts_kernel<<<(cnt + 255) / 256, 256>>>();
    zero_accum_kernel<<<(NN * EMB + 255) / 256, 256>>>();
    count_kernel<<<(EE + 255) / 256, 256>>>(srcp, dstp, etype);
    invert_kernel<<<(cnt + 255) / 256, 256>>>();
    assign_kernel<<<(NN + 255) / 256, 256>>>();
    fill_kernel<<<(EE + 255) / 256, 256>>>(srcp, dstp, etype);
    hid_kernel<<<(EE + WPB - 1) / WPB, WPB * 32>>>(etype, edist, W1, b1);
    w2t_kernel<<<(32 * 1024 + 255) / 256, 256>>>(W2);
    fc_kernel<<<(NN + WPB - 1) / WPB, WPB * 32>>>(x, fcW, fcb);

    for (int l = 0; l < NLAY; l++) {
        int p = l & 1;
        fused_kernel<<<(NN + WPB - 1) / WPB, WPB * 32, SM_FLOATS * 4>>>(
            p, rW + (size_t)l * NREL * 1024, b2);
        combine_kernel<<<(NN + WPB - 1) / WPB, WPB * 32>>>(
            p, rroot + (size_t)l * 1024, rbias + (size_t)l * 32,
            nroot + (size_t)l * 1024, nbias + (size_t)l * 32,
            (l == NLAY - 1) ? out : nullptr);
    }
}

// round 5
// speedup vs baseline: 1.5916x; 1.5916x over previous
#include <cuda_runtime.h>
#include <cuda_fp16.h>
#include <cstdint>

#define NN   50000
#define EE   400000
#define EMB  32
#define NREL 8
#define NLAY 5
#define WPB  8            // warps per block (256 threads)

typedef unsigned int u32;

// ---------------- scratch (static device globals; no allocations) ----------
__device__ float   g_W2t[32 * 1024];             // W2 transposed to [i][(k,o)]
__device__ __half2 g_Gh[(size_t)NN * 512];       // 100 MB: G[n][k2][o] half2 over k-pairs
__device__ float   g_h[2][NN * EMB];
__device__ float   g_disc[NN * EMB];
__device__ float   g_agg[NN * EMB];
__device__ float   g_invdeg[NN];
__device__ float   g_invrel[NREL][NN];
__device__ int     g_counter;
// CSR by source (segments in arbitrary order)
__device__ int     g_outdeg[NN];
__device__ int     g_cursor[NN];
__device__ int     g_rowptr[NN];
__device__ int     g_ceid[EE];
__device__ int     g_cpdr[EE];                   // (rel<<20)|dst
__device__ float   g_cwn[EE];                    // invdeg[dst]
__device__ float   g_cwr[EE];                    // invrel[r][dst]
__device__ u32     g_chid2[(size_t)EE * 16];     // per-edge hidden, half2 pairs

__device__ __forceinline__ void red_add_v4(float* addr, float4 v) {
    asm volatile("red.global.add.v4.f32 [%0], {%1,%2,%3,%4};"
                 :: "l"(addr), "f"(v.x), "f"(v.y), "f"(v.z), "f"(v.w)
                 : "memory");
}

// ---------------- zero / counts ---------------------------------------------
__global__ void zero_counts_kernel() {
    int i = blockIdx.x * blockDim.x + threadIdx.x;
    if (i == 0) g_counter = 0;
    if (i < NN) { g_invdeg[i] = 0.f; g_outdeg[i] = 0; }
    if (i < NN * NREL) ((float*)g_invrel)[i] = 0.f;
}

__global__ void zero_accum_kernel() {
    int i = blockIdx.x * blockDim.x + threadIdx.x;
    if (i < NN * EMB) { g_disc[i] = 0.f; g_agg[i] = 0.f; }
}

__global__ void count_kernel(const int* __restrict__ src,
                             const int* __restrict__ dst,
                             const int* __restrict__ etype) {
    int e = blockIdx.x * blockDim.x + threadIdx.x;
    if (e >= EE) return;
    int d = dst[e], r = etype[e];
    atomicAdd(&g_invdeg[d], 1.f);
    atomicAdd(&g_invrel[r][d], 1.f);
    atomicAdd(&g_outdeg[src[e]], 1);
}

__global__ void invert_kernel() {
    int i = blockIdx.x * blockDim.x + threadIdx.x;
    if (i < NN) g_invdeg[i] = 1.f / fmaxf(g_invdeg[i], 1.f);
    if (i < NN * NREL) {
        float v = ((float*)g_invrel)[i];
        ((float*)g_invrel)[i] = 1.f / fmaxf(v, 1.f);
    }
}

// ---------------- rowptr via atomic segment assignment (order-free) ---------
__global__ void assign_kernel() {
    int i = blockIdx.x * blockDim.x + threadIdx.x;
    if (i >= NN) return;
    g_rowptr[i] = atomicAdd(&g_counter, g_outdeg[i]);
    g_cursor[i] = 0;
}

// ---------------- fill CSR ---------------------------------------------------
__global__ void fill_kernel(const int* __restrict__ src,
                            const int* __restrict__ dst,
                            const int* __restrict__ etype) {
    int e = blockIdx.x * blockDim.x + threadIdx.x;
    if (e >= EE) return;
    int s = src[e];
    int pos = g_rowptr[s] + atomicAdd(&g_cursor[s], 1);
    g_ceid[pos] = e;
    g_cpdr[pos] = (etype[e] << 20) | dst[e];
}

// ---------------- per-edge hidden (layer-invariant) + scales ----------------
__global__ __launch_bounds__(WPB * 32) void hid_kernel(
    const int* __restrict__ etype, const float* __restrict__ edist,
    const float* __restrict__ W1, const float* __restrict__ b1) {
    int warp = threadIdx.x >> 5, lane = threadIdx.x & 31;
    int pos = blockIdx.x * WPB + warp;
    if (pos >= EE) return;
    int e = g_ceid[pos];
    int r = etype[e];
    float dd = edist[e];
    float h = fmaxf(dd * W1[lane] + W1[(1 + r) * 32 + lane] + b1[lane], 0.f);
    // pack lane pairs into half2
    float hlo = __shfl_sync(0xffffffffu, h, 2 * (lane & 15));
    float hhi = __shfl_sync(0xffffffffu, h, 2 * (lane & 15) + 1);
    if (lane < 16) {
        __half2 hp = __floats2half2_rn(hlo, hhi);
        g_chid2[(size_t)pos * 16 + lane] = *(u32*)&hp;
    }
    if (lane == 0) {
        int dn = g_cpdr[pos] & 0xFFFFF;
        g_cwn[pos] = g_invdeg[dn];
        g_cwr[pos] = g_invrel[r][dn];
    }
}

// ---------------- transpose W2: g_W2t[i][(k,o)] = W2[k][i*32+o] -------------
__global__ void w2t_kernel(const float* __restrict__ W2) {
    int idx = blockIdx.x * blockDim.x + threadIdx.x;
    if (idx >= 32 * 1024) return;
    int i = idx >> 10, rest = idx & 1023;
    g_W2t[idx] = W2[(rest >> 5) * 1024 + i * 32 + (rest & 31)];
}

// ---------------- h0 = relu(x @ fc_W + fc_b) --------------------------------
__global__ __launch_bounds__(WPB * 32) void fc_kernel(
    const float* __restrict__ x, const float* __restrict__ W,
    const float* __restrict__ b) {
    int warp = threadIdx.x >> 5, lane = threadIdx.x & 31;
    int n = blockIdx.x * WPB + warp;
    if (n >= NN) return;
    float xv = x[n * 32 + lane];
    float acc = b[lane];
#pragma unroll
    for (int k = 0; k < 32; k++)
        acc = fmaf(__shfl_sync(0xffffffffu, xv, k), W[k * 32 + lane], acc);
    g_h[0][n * 32 + lane] = fmaxf(acc, 0.f);
}

// ---------------- G = h @ W2t, fp16 output ----------------------------------
// grid (ceil(N/32), 4), block 256. Tile: 32 nodes x 256 flat cols.
__global__ __launch_bounds__(256) void gemmG_kernel(int p) {
    __shared__ float sh[32][33];
    __shared__ float sW[32][256];
    int t = threadIdx.x;
    int n0 = blockIdx.x * 32;
    int by = blockIdx.y;
    int c0 = by * 256;

    {   // load h tile (32x32) as float4
        int node = t >> 3, k = (t & 7) * 4;
        float4 v = make_float4(0.f, 0.f, 0.f, 0.f);
        if (n0 + node < NN)
            v = *(const float4*)&g_h[p][(size_t)(n0 + node) * 32 + k];
        sh[node][k] = v.x; sh[node][k + 1] = v.y;
        sh[node][k + 2] = v.z; sh[node][k + 3] = v.w;
    }
#pragma unroll
    for (int j = 0; j < 8; j++) {
        int f4 = t + j * 256;
        int flat = f4 * 4;
        int k = flat >> 8, c = flat & 255;
        *(float4*)&sW[k][c] = *(const float4*)&g_W2t[k * 1024 + c0 + c];
    }
    __syncthreads();

    int lane = t & 31, wg = t >> 5;
    float acc[4][8];
#pragma unroll
    for (int j = 0; j < 4; j++)
#pragma unroll
        for (int c = 0; c < 8; c++) acc[j][c] = 0.f;

#pragma unroll
    for (int k = 0; k < 32; k++) {
        float a0 = sh[wg * 4 + 0][k];
        float a1 = sh[wg * 4 + 1][k];
        float a2 = sh[wg * 4 + 2][k];
        float a3 = sh[wg * 4 + 3][k];
#pragma unroll
        for (int c = 0; c < 8; c++) {
            float w = sW[k][lane + 32 * c];
            acc[0][c] = fmaf(a0, w, acc[0][c]);
            acc[1][c] = fmaf(a1, w, acc[1][c]);
            acc[2][c] = fmaf(a2, w, acc[2][c]);
            acc[3][c] = fmaf(a3, w, acc[3][c]);
        }
    }
    // write half2 pairs over k: flat col = c0 + lane + 32c -> k = 8*by + c, o = lane
    // h2 index = n*512 + (4*by + c2)*32 + lane
#pragma unroll
    for (int j = 0; j < 4; j++) {
        int n = n0 + wg * 4 + j;
        if (n < NN) {
#pragma unroll
            for (int c2 = 0; c2 < 4; c2++)
                g_Gh[(size_t)n * 512 + (4 * by + c2) * 32 + lane] =
                    __floats2half2_rn(acc[j][2 * c2], acc[j][2 * c2 + 1]);
        }
    }
}

// ---------------- per-layer edge kernel (warp per source) -------------------
__global__ __launch_bounds__(WPB * 32) void edge_kernel(
    int p, const float* __restrict__ rW,   // [R,32,32] this layer
    const float* __restrict__ b2) {
    __shared__ float sWr[NREL * 1024];     // 32 KB
    __shared__ float sXr[WPB][NREL][32];   // 8 KB
    __shared__ float sb2[1024];            // 4 KB

    int t = threadIdx.x;
#pragma unroll
    for (int j = 0; j < 8; j++)
        *(float4*)&sWr[(t + j * 256) * 4] = *(const float4*)&rW[(t + j * 256) * 4];
    *(float4*)&sb2[t * 4] = *(const float4*)&b2[t * 4];
    __syncthreads();

    int warp = t >> 5, lane = t & 31;
    int n = blockIdx.x * WPB + warp;
    if (n >= NN) return;

    float hs = g_h[p][(size_t)n * 32 + lane];

    // preload G row into registers (fp16 -> fp32 once)
    float Greg[32];
    {
        const __half2* gr = &g_Gh[(size_t)n * 512];
#pragma unroll
        for (int k2 = 0; k2 < 16; k2++) {
            float2 f = __half22float2(gr[k2 * 32 + lane]);
            Greg[2 * k2]     = f.x;
            Greg[2 * k2 + 1] = f.y;
        }
    }

    // RGCN per-relation source messages + NNConv bias row
    float B = 0.f;
    {
        float xr[NREL];
#pragma unroll
        for (int r = 0; r < NREL; r++) xr[r] = 0.f;
#pragma unroll
        for (int i = 0; i < 32; i++) {
            float hv = __shfl_sync(0xffffffffu, hs, i);
            B = fmaf(hv, sb2[i * 32 + lane], B);
#pragma unroll
            for (int r = 0; r < NREL; r++)
                xr[r] = fmaf(hv, sWr[r * 1024 + i * 32 + lane], xr[r]);
        }
#pragma unroll
        for (int r = 0; r < NREL; r++) sXr[warp][r][lane] = xr[r];
    }
    __syncwarp();

    int beg = g_rowptr[n];
    int end = beg + g_outdeg[n];
    int q4 = (lane & 7) * 4;
    for (int pos = beg; pos < end; pos++) {
        int   pdr = g_cpdr[pos];
        int   d   = pdr & 0xFFFFF;
        int   r   = pdr >> 20;
        float wn  = g_cwn[pos];
        float wr  = g_cwr[pos];

        u32 myh = (lane < 16) ? g_chid2[(size_t)pos * 16 + lane] : 0u;

        float m0 = 0.f, m1 = 0.f;
#pragma unroll
        for (int k2 = 0; k2 < 16; k2++) {
            u32 hu = __shfl_sync(0xffffffffu, myh, k2);
            float2 hf = __half22float2(*(__half2*)&hu);
            m0 = fmaf(hf.x, Greg[2 * k2],     m0);
            m1 = fmaf(hf.y, Greg[2 * k2 + 1], m1);
        }
        float mm = (m0 + m1 + B) * wn;                 // NNConv contribution
        float dv = sXr[warp][r][lane] * wr;            // RGCN contribution

        // warp transpose to float4 and vector-reduce
        float a0 = __shfl_sync(0xffffffffu, mm, q4 + 0);
        float a1 = __shfl_sync(0xffffffffu, mm, q4 + 1);
        float a2 = __shfl_sync(0xffffffffu, mm, q4 + 2);
        float a3 = __shfl_sync(0xffffffffu, mm, q4 + 3);
        float b0 = __shfl_sync(0xffffffffu, dv, q4 + 0);
        float b1 = __shfl_sync(0xffffffffu, dv, q4 + 1);
        float b2v = __shfl_sync(0xffffffffu, dv, q4 + 2);
        float b3 = __shfl_sync(0xffffffffu, dv, q4 + 3);
        if (lane < 8)
            red_add_v4(&g_agg[(size_t)d * 32 + q4], make_float4(a0, a1, a2, a3));
        else if (lane < 16)
            red_add_v4(&g_disc[(size_t)d * 32 + q4], make_float4(b0, b1, b2v, b3));
    }
}

// ---------------- combine: root transforms + residual + reset accum ---------
__global__ __launch_bounds__(WPB * 32) void combine_kernel(
    int p, const float* __restrict__ rroot, const float* __restrict__ rbias,
    const float* __restrict__ nroot, const float* __restrict__ nbias,
    float* __restrict__ out_final) {
    int warp = threadIdx.x >> 5, lane = threadIdx.x & 31;
    int n = blockIdx.x * WPB + warp;
    if (n >= NN) return;
    size_t idx = (size_t)n * 32 + lane;
    float hv = g_h[p][idx];
    float accD = rbias[lane];
    float accN = nbias[lane];
#pragma unroll
    for (int k = 0; k < 32; k++) {
        float v = __shfl_sync(0xffffffffu, hv, k);
        accD = fmaf(v, rroot[k * 32 + lane], accD);
        accN = fmaf(v, nroot[k * 32 + lane], accN);
    }
    float v = hv + fmaxf(accD + g_disc[idx], 0.f)
                 + fmaxf(accN + g_agg[idx], 0.f);
    g_disc[idx] = 0.f;
    g_agg[idx]  = 0.f;
    if (out_final) out_final[idx] = v;
    else           g_h[p ^ 1][idx] = v;
}

// ---------------- host launch ------------------------------------------------
extern "C" void kernel_launch(void* const* d_in, const int* in_sizes, int n_in,
                              void* d_out, int out_size) {
    const float* x     = (const float*)d_in[0];
    const int*   eidx  = (const int*)  d_in[1];   // [2,E]: src then dst
    const int*   etype = (const int*)  d_in[2];
    const float* edist = (const float*)d_in[3];
    const float* fcW   = (const float*)d_in[4];
    const float* fcb   = (const float*)d_in[5];
    const float* rW    = (const float*)d_in[6];   // [L,R,32,32]
    const float* rroot = (const float*)d_in[7];   // [L,32,32]
    const float* rbias = (const float*)d_in[8];   // [L,32]
    const float* W1    = (const float*)d_in[9];   // [9,32]
    const float* b1    = (const float*)d_in[10];  // [32]
    const float* W2    = (const float*)d_in[11];  // [32,1024]
    const float* b2    = (const float*)d_in[12];  // [1024]
    const float* nroot = (const float*)d_in[13];  // [L,32,32]
    const float* nbias = (const float*)d_in[14];  // [L,32]
    float* out = (float*)d_out;

    const int* srcp = eidx;
    const int* dstp = eidx + EE;

    int cnt = NN * NREL;
    zero_counts_kernel<<<(cnt + 255) / 256, 256>>>();
    zero_accum_kernel<<<(NN * EMB + 255) / 256, 256>>>();
    count_kernel<<<(EE + 255) / 256, 256>>>(srcp, dstp, etype);
    invert_kernel<<<(cnt + 255) / 256, 256>>>();
    assign_kernel<<<(NN + 255) / 256, 256>>>();
    fill_kernel<<<(EE + 255) / 256, 256>>>(srcp, dstp, etype);
    hid_kernel<<<(EE + WPB - 1) / WPB, WPB * 32>>>(etype, edist, W1, b1);
    w2t_kernel<<<(32 * 1024 + 255) / 256, 256>>>(W2);
    fc_kernel<<<(NN + WPB - 1) / WPB, WPB * 32>>>(x, fcW, fcb);

    for (int l = 0; l < NLAY; l++) {
        int p = l & 1;
        gemmG_kernel<<<dim3((NN + 31) / 32, 4), 256>>>(p);
        edge_kernel<<<(NN + WPB - 1) / WPB, WPB * 32>>>(
            p, rW + (size_t)l * NREL * 1024, b2);
        combine_kernel<<<(NN + WPB - 1) / WPB, WPB * 32>>>(
            p, rroot + (size_t)l * 1024, rbias + (size_t)l * 32,
            nroot + (size_t)l * 1024, nbias + (size_t)l * 32,
            (l == NLAY - 1) ? out : nullptr);
    }
}

// round 6
// speedup vs baseline: 1.8905x; 1.1878x over previous
#include <cuda_runtime.h>
#include <cuda_fp16.h>
#include <cstdint>

#define NN    50000
#define EE    400000
#define NREL  8
#define NLAY  5
#define WPB   8            // warps per block (256 threads)
#define WCOLS 1536         // 1024 G | 256 Xr | 32 B | 224 pad
#define H2N   768          // half2 per node row

typedef unsigned int u32;

// ---------------- scratch (static device globals; no allocations) ----------
__device__ float   g_Wcat[NLAY][32 * WCOLS];     // fused weights per layer
__device__ __half2 g_Gh[(size_t)NN * H2N];       // 153 MB: per-node G|Xr|B fp16
__device__ float   g_h[2][NN * 32];
__device__ float   g_disc[NN * 32];
__device__ float   g_agg[NN * 32];
__device__ float   g_invdeg[NN];
__device__ float   g_invrel[NREL][NN];
__device__ int     g_counter;
__device__ int     g_outdeg[NN];
__device__ int     g_cursor[NN];
__device__ int     g_rowptr[NN];
__device__ int     g_ceid[EE];
__device__ int4    g_erec[EE];                   // {(r<<20)|d, wn, wr, 0}
__device__ u32     g_chid2[(size_t)EE * 16];     // per-edge hidden, half2 pairs

__device__ __forceinline__ void red_add_v4(float* addr, float4 v) {
    asm volatile("red.global.add.v4.f32 [%0], {%1,%2,%3,%4};"
                 :: "l"(addr), "f"(v.x), "f"(v.y), "f"(v.z), "f"(v.w)
                 : "memory");
}

// ---------------- init: zero everything -------------------------------------
__global__ void init_kernel() {
    int i = blockIdx.x * blockDim.x + threadIdx.x;
    if (i == 0) g_counter = 0;
    if (i < NN) { g_invdeg[i] = 0.f; g_outdeg[i] = 0; }
    if (i < NN * NREL) ((float*)g_invrel)[i] = 0.f;
    if (i < NN * 32) { g_disc[i] = 0.f; g_agg[i] = 0.f; }
}

__global__ void count_kernel(const int* __restrict__ src,
                             const int* __restrict__ dst,
                             const int* __restrict__ etype) {
    int e = blockIdx.x * blockDim.x + threadIdx.x;
    if (e >= EE) return;
    int d = dst[e], r = etype[e];
    atomicAdd(&g_invdeg[d], 1.f);
    atomicAdd(&g_invrel[r][d], 1.f);
    atomicAdd(&g_outdeg[src[e]], 1);
}

__global__ void invert_kernel() {
    int i = blockIdx.x * blockDim.x + threadIdx.x;
    if (i < NN) g_invdeg[i] = 1.f / fmaxf(g_invdeg[i], 1.f);
    if (i < NN * NREL) {
        float v = ((float*)g_invrel)[i];
        ((float*)g_invrel)[i] = 1.f / fmaxf(v, 1.f);
    }
}

// rowptr via atomic segment assignment (segment order irrelevant)
__global__ void assign_kernel() {
    int i = blockIdx.x * blockDim.x + threadIdx.x;
    if (i >= NN) return;
    g_rowptr[i] = atomicAdd(&g_counter, g_outdeg[i]);
    g_cursor[i] = 0;
}

__global__ void fill_kernel(const int* __restrict__ src,
                            const int* __restrict__ dst,
                            const int* __restrict__ etype) {
    int e = blockIdx.x * blockDim.x + threadIdx.x;
    if (e >= EE) return;
    int s = src[e], d = dst[e], r = etype[e];
    int pos = g_rowptr[s] + atomicAdd(&g_cursor[s], 1);
    g_ceid[pos] = e;
    int4 rec;
    rec.x = (r << 20) | d;
    rec.y = __float_as_int(g_invdeg[d]);
    rec.z = __float_as_int(g_invrel[r][d]);
    rec.w = 0;
    g_erec[pos] = rec;
}

// per-edge hidden (layer-invariant), packed half2 over k-pairs
__global__ __launch_bounds__(WPB * 32) void hid_kernel(
    const int* __restrict__ etype, const float* __restrict__ edist,
    const float* __restrict__ W1, const float* __restrict__ b1) {
    int warp = threadIdx.x >> 5, lane = threadIdx.x & 31;
    int pos = blockIdx.x * WPB + warp;
    if (pos >= EE) return;
    int e = g_ceid[pos];
    int r = etype[e];
    float dd = edist[e];
    float h = fmaxf(dd * W1[lane] + W1[(1 + r) * 32 + lane] + b1[lane], 0.f);
    float hlo = __shfl_sync(0xffffffffu, h, 2 * (lane & 15));
    float hhi = __shfl_sync(0xffffffffu, h, 2 * (lane & 15) + 1);
    if (lane < 16) {
        __half2 hp = __floats2half2_rn(hlo, hhi);
        g_chid2[(size_t)pos * 16 + lane] = *(u32*)&hp;
    }
}

// build fused weight matrix for all layers
__global__ void wcat_kernel(const float* __restrict__ W2,
                            const float* __restrict__ rW,
                            const float* __restrict__ b2) {
    int idx = blockIdx.x * blockDim.x + threadIdx.x;
    if (idx >= NLAY * 32 * WCOLS) return;
    int l = idx / (32 * WCOLS);
    int rem = idx % (32 * WCOLS);
    int i = rem / WCOLS, c = rem % WCOLS;
    float v = 0.f;
    if (c < 1024)                       // G: W2t[i][k*32+o] = W2[k][i*32+o]
        v = W2[(c >> 5) * 1024 + i * 32 + (c & 31)];
    else if (c < 1280) {                // Xr: rW[l][r][i][o]
        int r = (c - 1024) >> 5;
        v = rW[((size_t)(l * NREL + r) * 32 + i) * 32 + (c & 31)];
    } else if (c < 1312)                // B: b2[i*32+o]
        v = b2[i * 32 + (c & 31)];
    g_Wcat[l][i * WCOLS + c] = v;
}

// ---------------- h0 = relu(x @ fc_W + fc_b) --------------------------------
__global__ __launch_bounds__(WPB * 32) void fc_kernel(
    const float* __restrict__ x, const float* __restrict__ W,
    const float* __restrict__ b) {
    int warp = threadIdx.x >> 5, lane = threadIdx.x & 31;
    int n = blockIdx.x * WPB + warp;
    if (n >= NN) return;
    float xv = x[n * 32 + lane];
    float acc = b[lane];
#pragma unroll
    for (int k = 0; k < 32; k++)
        acc = fmaf(__shfl_sync(0xffffffffu, xv, k), W[k * 32 + lane], acc);
    g_h[0][n * 32 + lane] = fmaxf(acc, 0.f);
}

// ---------------- [G|Xr|B] = h @ Wcat[l], fp16 output -----------------------
// grid (ceil(N/32), 6), block 256. Tile: 32 nodes x 256 flat cols.
__global__ __launch_bounds__(256) void gemmG_kernel(int p, int l) {
    __shared__ float sh[32][33];
    __shared__ float sW[32][256];
    int t = threadIdx.x;
    int n0 = blockIdx.x * 32;
    int by = blockIdx.y;
    int c0 = by * 256;
    const float* Wc = g_Wcat[l];

    {   // load h tile (32x32) as float4
        int node = t >> 3, k = (t & 7) * 4;
        float4 v = make_float4(0.f, 0.f, 0.f, 0.f);
        if (n0 + node < NN)
            v = *(const float4*)&g_h[p][(size_t)(n0 + node) * 32 + k];
        sh[node][k] = v.x; sh[node][k + 1] = v.y;
        sh[node][k + 2] = v.z; sh[node][k + 3] = v.w;
    }
#pragma unroll
    for (int j = 0; j < 8; j++) {
        int f4 = t + j * 256;
        int flat = f4 * 4;
        int k = flat >> 8, c = flat & 255;
        *(float4*)&sW[k][c] = *(const float4*)&Wc[k * WCOLS + c0 + c];
    }
    __syncthreads();

    int lane = t & 31, wg = t >> 5;
    float acc[4][8];
#pragma unroll
    for (int j = 0; j < 4; j++)
#pragma unroll
        for (int c = 0; c < 8; c++) acc[j][c] = 0.f;

#pragma unroll
    for (int k = 0; k < 32; k++) {
        float a0 = sh[wg * 4 + 0][k];
        float a1 = sh[wg * 4 + 1][k];
        float a2 = sh[wg * 4 + 2][k];
        float a3 = sh[wg * 4 + 3][k];
#pragma unroll
        for (int c = 0; c < 8; c++) {
            float w = sW[k][lane + 32 * c];
            acc[0][c] = fmaf(a0, w, acc[0][c]);
            acc[1][c] = fmaf(a1, w, acc[1][c]);
            acc[2][c] = fmaf(a2, w, acc[2][c]);
            acc[3][c] = fmaf(a3, w, acc[3][c]);
        }
    }
#pragma unroll
    for (int j = 0; j < 4; j++) {
        int n = n0 + wg * 4 + j;
        if (n < NN) {
#pragma unroll
            for (int c2 = 0; c2 < 4; c2++)
                g_Gh[(size_t)n * H2N + (4 * by + c2) * 32 + lane] =
                    __floats2half2_rn(acc[j][2 * c2], acc[j][2 * c2 + 1]);
        }
    }
}

// ---------------- per-layer edge kernel (warp per source, lean) -------------
__global__ __launch_bounds__(256) void edge_kernel() {
    __shared__ float sXr[WPB][NREL][32];     // 8 KB
    __shared__ float sT[WPB][2][4][32];      // 8 KB (double-buffered transpose)
    int t = threadIdx.x, warp = t >> 5, lane = t & 31;
    int n = blockIdx.x * WPB + warp;
    if (n >= NN) return;

    const __half2* gr = &g_Gh[(size_t)n * H2N];
    __half2 G2[16];
#pragma unroll
    for (int k2 = 0; k2 < 16; k2++) G2[k2] = gr[k2 * 32 + lane];
#pragma unroll
    for (int c2 = 0; c2 < 4; c2++) {
        float2 xp = __half22float2(gr[(16 + c2) * 32 + lane]);
        sXr[warp][2 * c2][lane]     = xp.x;
        sXr[warp][2 * c2 + 1][lane] = xp.y;
    }
    float B = __low2float(gr[640 + lane]);
    __syncwarp();

    int beg = g_rowptr[n], end = beg + g_outdeg[n];
    int g = lane >> 3, q4 = (lane & 7) * 4;
    int buf = 0;
    int pos = beg;
    for (; pos + 2 <= end; pos += 2, buf ^= 1) {
        int4 eA = g_erec[pos], eB = g_erec[pos + 1];
        u32 myh = g_chid2[(size_t)pos * 16 + lane];  // lanes 0-15: A, 16-31: B
        __half2 accA = __float2half2_rn(0.f), accB = accA;
#pragma unroll
        for (int k2 = 0; k2 < 16; k2++) {
            u32 ha = __shfl_sync(0xffffffffu, myh, k2);
            u32 hb = __shfl_sync(0xffffffffu, myh, 16 + k2);
            accA = __hfma2(*(__half2*)&ha, G2[k2], accA);
            accB = __hfma2(*(__half2*)&hb, G2[k2], accB);
        }
        int dA = eA.x & 0xFFFFF, rA = eA.x >> 20;
        int dB = eB.x & 0xFFFFF, rB = eB.x >> 20;
        float2 fA = __half22float2(accA), fB = __half22float2(accB);
        float mmA = (fA.x + fA.y + B) * __int_as_float(eA.y);
        float mmB = (fB.x + fB.y + B) * __int_as_float(eB.y);
        float dvA = sXr[warp][rA][lane] * __int_as_float(eA.z);
        float dvB = sXr[warp][rB][lane] * __int_as_float(eB.z);
        sT[warp][buf][0][lane] = mmA;
        sT[warp][buf][1][lane] = dvA;
        sT[warp][buf][2][lane] = mmB;
        sT[warp][buf][3][lane] = dvB;
        __syncwarp();
        float4 v = *(float4*)&sT[warp][buf][g][q4];
        int   dsel = (g < 2) ? dA : dB;
        float* base = (g & 1) ? g_disc : g_agg;
        red_add_v4(base + (size_t)dsel * 32 + q4, v);
    }
    if (pos < end) {   // tail single edge
        int4 eA = g_erec[pos];
        u32 myh = g_chid2[(size_t)pos * 16 + (lane & 15)];
        __half2 accA = __float2half2_rn(0.f);
#pragma unroll
        for (int k2 = 0; k2 < 16; k2++) {
            u32 ha = __shfl_sync(0xffffffffu, myh, k2);
            accA = __hfma2(*(__half2*)&ha, G2[k2], accA);
        }
        int dA = eA.x & 0xFFFFF, rA = eA.x >> 20;
        float2 fA = __half22float2(accA);
        float mmA = (fA.x + fA.y + B) * __int_as_float(eA.y);
        float dvA = sXr[warp][rA][lane] * __int_as_float(eA.z);
        sT[warp][buf][0][lane] = mmA;
        sT[warp][buf][1][lane] = dvA;
        __syncwarp();
        if (lane < 16) {
            float4 v = *(float4*)&sT[warp][buf][g][q4];
            float* base = (g & 1) ? g_disc : g_agg;
            red_add_v4(base + (size_t)dA * 32 + q4, v);
        }
    }
}

// ---------------- combine: root transforms + residual + reset accum ---------
__global__ __launch_bounds__(WPB * 32) void combine_kernel(
    int p, const float* __restrict__ rroot, const float* __restrict__ rbias,
    const float* __restrict__ nroot, const float* __restrict__ nbias,
    float* __restrict__ out_final) {
    int warp = threadIdx.x >> 5, lane = threadIdx.x & 31;
    int n = blockIdx.x * WPB + warp;
    if (n >= NN) return;
    size_t idx = (size_t)n * 32 + lane;
    float hv = g_h[p][idx];
    float accD = rbias[lane];
    float accN = nbias[lane];
#pragma unroll
    for (int k = 0; k < 32; k++) {
        float v = __shfl_sync(0xffffffffu, hv, k);
        accD = fmaf(v, rroot[k * 32 + lane], accD);
        accN = fmaf(v, nroot[k * 32 + lane], accN);
    }
    float v = hv + fmaxf(accD + g_disc[idx], 0.f)
                 + fmaxf(accN + g_agg[idx], 0.f);
    g_disc[idx] = 0.f;
    g_agg[idx]  = 0.f;
    if (out_final) out_final[idx] = v;
    else           g_h[p ^ 1][idx] = v;
}

// ---------------- host launch ------------------------------------------------
extern "C" void kernel_launch(void* const* d_in, const int* in_sizes, int n_in,
                              void* d_out, int out_size) {
    const float* x     = (const float*)d_in[0];
    const int*   eidx  = (const int*)  d_in[1];   // [2,E]: src then dst
    const int*   etype = (const int*)  d_in[2];
    const float* edist = (const float*)d_in[3];
    const float* fcW   = (const float*)d_in[4];
    const float* fcb   = (const float*)d_in[5];
    const float* rW    = (const float*)d_in[6];   // [L,R,32,32]
    const float* rroot = (const float*)d_in[7];   // [L,32,32]
    const float* rbias = (const float*)d_in[8];   // [L,32]
    const float* W1    = (const float*)d_in[9];   // [9,32]
    const float* b1    = (const float*)d_in[10];  // [32]
    const float* W2    = (const float*)d_in[11];  // [32,1024]
    const float* b2    = (const float*)d_in[12];  // [1024]
    const float* nroot = (const float*)d_in[13];  // [L,32,32]
    const float* nbias = (const float*)d_in[14];  // [L,32]
    float* out = (float*)d_out;

    const int* srcp = eidx;
    const int* dstp = eidx + EE;

    init_kernel<<<(NN * 32 + 255) / 256, 256>>>();
    count_kernel<<<(EE + 255) / 256, 256>>>(srcp, dstp, etype);
    invert_kernel<<<(NN * NREL + 255) / 256, 256>>>();
    assign_kernel<<<(NN + 255) / 256, 256>>>();
    fill_kernel<<<(EE + 255) / 256, 256>>>(srcp, dstp, etype);
    hid_kernel<<<(EE + WPB - 1) / WPB, WPB * 32>>>(etype, edist, W1, b1);
    wcat_kernel<<<(NLAY * 32 * WCOLS + 255) / 256, 256>>>(W2, rW, b2);
    fc_kernel<<<(NN + WPB - 1) / WPB, WPB * 32>>>(x, fcW, fcb);

    for (int l = 0; l < NLAY; l++) {
        int p = l & 1;
        gemmG_kernel<<<dim3((NN + 31) / 32, 6), 256>>>(p, l);
        edge_kernel<<<(NN + WPB - 1) / WPB, WPB * 32>>>();
        combine_kernel<<<(NN + WPB - 1) / WPB, WPB * 32>>>(
            p, rroot + (size_t)l * 1024, rbias + (size_t)l * 32,
            nroot + (size_t)l * 1024, nbias + (size_t)l * 32,
            (l == NLAY - 1) ? out : nullptr);
    }
}

// round 7
// speedup vs baseline: 2.0899x; 1.1055x over previous
#include <cuda_runtime.h>
#include <cuda_fp16.h>
#include <cstdint>

#define NN    50000
#define EE    400000
#define NREL  8
#define NLAY  5
#define WPB   8            // warps per block (256 threads)
#define NCOL  1536         // GEMM N: 1024 G | 256 Xr | 64 B | 64 roots | pad
#define H2N   768          // half2 per node row of g_Gh

typedef unsigned int u32;

// ---------------- scratch (static device globals; no allocations) ----------
__device__ __half   g_WcatH[NLAY][NCOL * 32];    // fused fp16 weights, col-major [j][i]
__device__ __half2  g_Gh[(size_t)NN * H2N];      // 153 MB: per-node G|Xr|B|roots fp16
__device__ float    g_h[2][NN * 32];
__device__ float    g_disc[NN * 32];
__device__ float    g_agg[NN * 32];
__device__ float    g_invdeg[NN];
__device__ float    g_invrel[NREL][NN];
__device__ int      g_counter;
__device__ int      g_outdeg[NN];
__device__ int      g_cursor[NN];
__device__ int      g_rowptr[NN];
__device__ int      g_ceid[EE];
__device__ int4     g_erec[EE];                  // {(r<<20)|d, wn, wr, 0}
__device__ u32      g_chid2[(size_t)EE * 16];    // per-edge hidden, half2 pairs

__device__ __forceinline__ void red_add_v4(float* addr, float4 v) {
    asm volatile("red.global.add.v4.f32 [%0], {%1,%2,%3,%4};"
                 :: "l"(addr), "f"(v.x), "f"(v.y), "f"(v.z), "f"(v.w)
                 : "memory");
}

__device__ __forceinline__ u32 pack_h2(float a, float b) {
    __half2 h = __floats2half2_rn(a, b);
    return *(u32*)&h;
}

// ---------------- init / counts ----------------------------------------------
__global__ void init_kernel() {
    int i = blockIdx.x * blockDim.x + threadIdx.x;
    if (i == 0) g_counter = 0;
    if (i < NN) { g_invdeg[i] = 0.f; g_outdeg[i] = 0; }
    if (i < NN * NREL) ((float*)g_invrel)[i] = 0.f;
    if (i < NN * 32) { g_disc[i] = 0.f; g_agg[i] = 0.f; }
}

__global__ void count_kernel(const int* __restrict__ src,
                             const int* __restrict__ dst,
                             const int* __restrict__ etype) {
    int e = blockIdx.x * blockDim.x + threadIdx.x;
    if (e >= EE) return;
    int d = dst[e], r = etype[e];
    atomicAdd(&g_invdeg[d], 1.f);
    atomicAdd(&g_invrel[r][d], 1.f);
    atomicAdd(&g_outdeg[src[e]], 1);
}

__global__ void invert_kernel() {
    int i = blockIdx.x * blockDim.x + threadIdx.x;
    if (i < NN) g_invdeg[i] = 1.f / fmaxf(g_invdeg[i], 1.f);
    if (i < NN * NREL) {
        float v = ((float*)g_invrel)[i];
        ((float*)g_invrel)[i] = 1.f / fmaxf(v, 1.f);
    }
}

__global__ void assign_kernel() {
    int i = blockIdx.x * blockDim.x + threadIdx.x;
    if (i >= NN) return;
    g_rowptr[i] = atomicAdd(&g_counter, g_outdeg[i]);
    g_cursor[i] = 0;
}

__global__ void fill_kernel(const int* __restrict__ src,
                            const int* __restrict__ dst,
                            const int* __restrict__ etype) {
    int e = blockIdx.x * blockDim.x + threadIdx.x;
    if (e >= EE) return;
    int s = src[e], d = dst[e], r = etype[e];
    int pos = g_rowptr[s] + atomicAdd(&g_cursor[s], 1);
    g_ceid[pos] = e;
    int4 rec;
    rec.x = (r << 20) | d;
    rec.y = __float_as_int(g_invdeg[d]);
    rec.z = __float_as_int(g_invrel[r][d]);
    rec.w = 0;
    g_erec[pos] = rec;
}

// per-edge hidden (layer-invariant), packed half2 over k-pairs
__global__ __launch_bounds__(WPB * 32) void hid_kernel(
    const int* __restrict__ etype, const float* __restrict__ edist,
    const float* __restrict__ W1, const float* __restrict__ b1) {
    int warp = threadIdx.x >> 5, lane = threadIdx.x & 31;
    int pos = blockIdx.x * WPB + warp;
    if (pos >= EE) return;
    int e = g_ceid[pos];
    int r = etype[e];
    float dd = edist[e];
    float h = fmaxf(dd * W1[lane] + W1[(1 + r) * 32 + lane] + b1[lane], 0.f);
    float hlo = __shfl_sync(0xffffffffu, h, 2 * (lane & 15));
    float hhi = __shfl_sync(0xffffffffu, h, 2 * (lane & 15) + 1);
    if (lane < 16)
        g_chid2[(size_t)pos * 16 + lane] = pack_h2(hlo, hhi);
}

// ---------------- build fused fp16 weight matrix, col-major [j][i] -----------
// GEMM column j -> pair index p=j>>1, parity par=j&1:
//   p<512      : G  : k=2*(p>>5)+par, o=p&31 -> W2[k*1024 + i*32 + o]
//   512<=p<640 : Xr : r=2*((p-512)>>5)+par, o=p&31 -> rW[l][r][i][o]
//   640<=p<672 : B  : o=p-640, par0 -> b2[i*32+o], par1 -> 0
//   672<=p<704 : roots: o=p-672, par0 -> rroot[l][i][o], par1 -> nroot[l][i][o]
//   else 0
__global__ void wcat_kernel(const float* __restrict__ W2,
                            const float* __restrict__ rW,
                            const float* __restrict__ b2,
                            const float* __restrict__ rroot,
                            const float* __restrict__ nroot) {
    int idx = blockIdx.x * blockDim.x + threadIdx.x;
    if (idx >= NLAY * NCOL * 32) return;
    int l = idx / (NCOL * 32);
    int rem = idx % (NCOL * 32);
    int j = rem >> 5, i = rem & 31;
    int p = j >> 1, par = j & 1;
    float v = 0.f;
    if (p < 512) {
        int k = 2 * (p >> 5) + par, o = p & 31;
        v = W2[k * 1024 + i * 32 + o];
    } else if (p < 640) {
        int r = 2 * ((p - 512) >> 5) + par, o = p & 31;
        v = rW[(((size_t)l * NREL + r) * 32 + i) * 32 + o];
    } else if (p < 672) {
        if (par == 0) v = b2[i * 32 + (p - 640)];
    } else if (p < 704) {
        int o = p - 672;
        v = par ? nroot[((size_t)l * 32 + i) * 32 + o]
                : rroot[((size_t)l * 32 + i) * 32 + o];
    }
    g_WcatH[l][rem] = __float2half(v);
}

// ---------------- h0 = relu(x @ fc_W + fc_b) --------------------------------
__global__ __launch_bounds__(WPB * 32) void fc_kernel(
    const float* __restrict__ x, const float* __restrict__ W,
    const float* __restrict__ b) {
    int warp = threadIdx.x >> 5, lane = threadIdx.x & 31;
    int n = blockIdx.x * WPB + warp;
    if (n >= NN) return;
    float xv = x[n * 32 + lane];
    float acc = b[lane];
#pragma unroll
    for (int k = 0; k < 32; k++)
        acc = fmaf(__shfl_sync(0xffffffffu, xv, k), W[k * 32 + lane], acc);
    g_h[0][n * 32 + lane] = fmaxf(acc, 0.f);
}

// ---------------- tensor-core GEMM: Gh = h @ WcatH --------------------------
// grid (ceil(N/32)=1563, 6), block 256 (8 warps as 2m x 4n).
// Warp tile 16(M) x 64(N); mma.sync.m16n8k16 fp16->fp32.
__global__ __launch_bounds__(256) void gemm_mma_kernel(int p, int l) {
    __shared__ __half2 sOut[32][132];      // padded: conflict-free stores
    int t = threadIdx.x, warp = t >> 5, lane = t & 31;
    int wm = warp >> 2, wn = warp & 3;
    int nblk = blockIdx.x * 32;
    int by = blockIdx.y;
    int m0 = wm * 16;
    int g = lane >> 2, tq = lane & 3;
    const __half* Wl = g_WcatH[l];
    const float* hp = g_h[p];

    float acc[8][4];
#pragma unroll
    for (int nt = 0; nt < 8; nt++)
#pragma unroll
        for (int c = 0; c < 4; c++) acc[nt][c] = 0.f;

    int nodeA = nblk + m0 + g;
    int nodeB = nodeA + 8;
    bool vA = nodeA < NN, vB = nodeB < NN;

#pragma unroll
    for (int kk = 0; kk < 2; kk++) {
        int kb = kk * 16 + tq * 2;
        float2 f00 = vA ? *(const float2*)&hp[(size_t)nodeA * 32 + kb]
                        : make_float2(0.f, 0.f);
        float2 f01 = vA ? *(const float2*)&hp[(size_t)nodeA * 32 + kb + 8]
                        : make_float2(0.f, 0.f);
        float2 f10 = vB ? *(const float2*)&hp[(size_t)nodeB * 32 + kb]
                        : make_float2(0.f, 0.f);
        float2 f11 = vB ? *(const float2*)&hp[(size_t)nodeB * 32 + kb + 8]
                        : make_float2(0.f, 0.f);
        u32 a0 = pack_h2(f00.x, f00.y);
        u32 a1 = pack_h2(f10.x, f10.y);
        u32 a2 = pack_h2(f01.x, f01.y);
        u32 a3 = pack_h2(f11.x, f11.y);
#pragma unroll
        for (int nt = 0; nt < 8; nt++) {
            int j = by * 256 + wn * 64 + nt * 8 + g;
            u32 b0 = *(const u32*)&Wl[j * 32 + kk * 16 + tq * 2];
            u32 b1 = *(const u32*)&Wl[j * 32 + kk * 16 + tq * 2 + 8];
            asm("mma.sync.aligned.m16n8k16.row.col.f32.f16.f16.f32 "
                "{%0,%1,%2,%3}, {%4,%5,%6,%7}, {%8,%9}, {%0,%1,%2,%3};"
                : "+f"(acc[nt][0]), "+f"(acc[nt][1]),
                  "+f"(acc[nt][2]), "+f"(acc[nt][3])
                : "r"(a0), "r"(a1), "r"(a2), "r"(a3), "r"(b0), "r"(b1));
        }
    }

    // stage to smem: thread owns (m0+g, pl) and (m0+8+g, pl)
#pragma unroll
    for (int nt = 0; nt < 8; nt++) {
        int pl = wn * 32 + nt * 4 + tq;
        __half2 lo = __floats2half2_rn(acc[nt][0], acc[nt][1]);
        __half2 hi = __floats2half2_rn(acc[nt][2], acc[nt][3]);
        sOut[m0 + g][pl] = lo;
        sOut[m0 + 8 + g][pl] = hi;
    }
    __syncthreads();

    // coalesced copy out: 32 rows x 128 h2; 8 threads per row
    int row = t >> 3, seg = t & 7;
    int node = nblk + row;
    if (node < NN) {
        __half2* dst = &g_Gh[(size_t)node * H2N + by * 128];
#pragma unroll
        for (int it = 0; it < 2; it++) {
            uint4 v = *(uint4*)&sOut[row][seg * 16 + it * 8];
            uint4 v2 = *(uint4*)&sOut[row][seg * 16 + it * 8 + 4];
            *(uint4*)&dst[seg * 16 + it * 8] = v;
            *(uint4*)&dst[seg * 16 + it * 8 + 4] = v2;
        }
    }
}

// ---------------- per-layer edge kernel (warp per source, lean) -------------
__global__ __launch_bounds__(256) void edge_kernel() {
    __shared__ float sXr[WPB][NREL][32];     // 8 KB
    __shared__ float sT[WPB][2][4][32];      // 8 KB (double-buffered transpose)
    int t = threadIdx.x, warp = t >> 5, lane = t & 31;
    int n = blockIdx.x * WPB + warp;
    if (n >= NN) return;

    const __half2* gr = &g_Gh[(size_t)n * H2N];
    __half2 G2[16];
#pragma unroll
    for (int k2 = 0; k2 < 16; k2++) G2[k2] = gr[k2 * 32 + lane];
#pragma unroll
    for (int c2 = 0; c2 < 4; c2++) {
        float2 xp = __half22float2(gr[(16 + c2) * 32 + lane]);
        sXr[warp][2 * c2][lane]     = xp.x;
        sXr[warp][2 * c2 + 1][lane] = xp.y;
    }
    float B = __low2float(gr[640 + lane]);
    __syncwarp();

    int beg = g_rowptr[n], end = beg + g_outdeg[n];
    int g = lane >> 3, q4 = (lane & 7) * 4;
    int buf = 0;
    int pos = beg;
    for (; pos + 2 <= end; pos += 2, buf ^= 1) {
        int4 eA = g_erec[pos], eB = g_erec[pos + 1];
        u32 myh = g_chid2[(size_t)pos * 16 + lane];  // lanes 0-15: A, 16-31: B
        __half2 accA = __float2half2_rn(0.f), accB = accA;
#pragma unroll
        for (int k2 = 0; k2 < 16; k2++) {
            u32 ha = __shfl_sync(0xffffffffu, myh, k2);
            u32 hb = __shfl_sync(0xffffffffu, myh, 16 + k2);
            accA = __hfma2(*(__half2*)&ha, G2[k2], accA);
            accB = __hfma2(*(__half2*)&hb, G2[k2], accB);
        }
        int dA = eA.x & 0xFFFFF, rA = eA.x >> 20;
        int dB = eB.x & 0xFFFFF, rB = eB.x >> 20;
        float2 fA = __half22float2(accA), fB = __half22float2(accB);
        float mmA = (fA.x + fA.y + B) * __int_as_float(eA.y);
        float mmB = (fB.x + fB.y + B) * __int_as_float(eB.y);
        float dvA = sXr[warp][rA][lane] * __int_as_float(eA.z);
        float dvB = sXr[warp][rB][lane] * __int_as_float(eB.z);
        sT[warp][buf][0][lane] = mmA;
        sT[warp][buf][1][lane] = dvA;
        sT[warp][buf][2][lane] = mmB;
        sT[warp][buf][3][lane] = dvB;
        __syncwarp();
        float4 v = *(float4*)&sT[warp][buf][g][q4];
        int   dsel = (g < 2) ? dA : dB;
        float* base = (g & 1) ? g_disc : g_agg;
        red_add_v4(base + (size_t)dsel * 32 + q4, v);
    }
    if (pos < end) {   // tail single edge
        int4 eA = g_erec[pos];
        u32 myh = g_chid2[(size_t)pos * 16 + (lane & 15)];
        __half2 accA = __float2half2_rn(0.f);
#pragma unroll
        for (int k2 = 0; k2 < 16; k2++) {
            u32 ha = __shfl_sync(0xffffffffu, myh, k2);
            accA = __hfma2(*(__half2*)&ha, G2[k2], accA);
        }
        int dA = eA.x & 0xFFFFF, rA = eA.x >> 20;
        float2 fA = __half22float2(accA);
        float mmA = (fA.x + fA.y + B) * __int_as_float(eA.y);
        float dvA = sXr[warp][rA][lane] * __int_as_float(eA.z);
        sT[warp][buf][0][lane] = mmA;
        sT[warp][buf][1][lane] = dvA;
        __syncwarp();
        if (lane < 16) {
            float4 v = *(float4*)&sT[warp][buf][g][q4];
            float* base = (g & 1) ? g_disc : g_agg;
            red_add_v4(base + (size_t)dA * 32 + q4, v);
        }
    }
}

// ---------------- combine: elementwise residual + reset accum ---------------
__global__ void combine_kernel(int p, const float* __restrict__ rbias,
                               const float* __restrict__ nbias,
                               float* __restrict__ out_final) {
    int idx = blockIdx.x * blockDim.x + threadIdx.x;
    if (idx >= NN * 32) return;
    int n = idx >> 5, o = idx & 31;
    float2 roots = __half22float2(g_Gh[(size_t)n * H2N + 672 + o]);
    float v = g_h[p][idx] + fmaxf(roots.x + rbias[o] + g_disc[idx], 0.f)
                          + fmaxf(roots.y + nbias[o] + g_agg[idx], 0.f);
    g_disc[idx] = 0.f;
    g_agg[idx]  = 0.f;
    if (out_final) out_final[idx] = v;
    else           g_h[p ^ 1][idx] = v;
}

// ---------------- host launch ------------------------------------------------
extern "C" void kernel_launch(void* const* d_in, const int* in_sizes, int n_in,
                              void* d_out, int out_size) {
    const float* x     = (const float*)d_in[0];
    const int*   eidx  = (const int*)  d_in[1];   // [2,E]: src then dst
    const int*   etype = (const int*)  d_in[2];
    const float* edist = (const float*)d_in[3];
    const float* fcW   = (const float*)d_in[4];
    const float* fcb   = (const float*)d_in[5];
    const float* rW    = (const float*)d_in[6];   // [L,R,32,32]
    const float* rroot = (const float*)d_in[7];   // [L,32,32]
    const float* rbias = (const float*)d_in[8];   // [L,32]
    const float* W1    = (const float*)d_in[9];   // [9,32]
    const float* b1    = (const float*)d_in[10];  // [32]
    const float* W2    = (const float*)d_in[11];  // [32,1024]
    const float* b2    = (const float*)d_in[12];  // [1024]
    const float* nroot = (const float*)d_in[13];  // [L,32,32]
    const float* nbias = (const float*)d_in[14];  // [L,32]
    float* out = (float*)d_out;

    const int* srcp = eidx;
    const int* dstp = eidx + EE;

    init_kernel<<<(NN * 32 + 255) / 256, 256>>>();
    count_kernel<<<(EE + 255) / 256, 256>>>(srcp, dstp, etype);
    invert_kernel<<<(NN * NREL + 255) / 256, 256>>>();
    assign_kernel<<<(NN + 255) / 256, 256>>>();
    fill_kernel<<<(EE + 255) / 256, 256>>>(srcp, dstp, etype);
    hid_kernel<<<(EE + WPB - 1) / WPB, WPB * 32>>>(etype, edist, W1, b1);
    wcat_kernel<<<(NLAY * NCOL * 32 + 255) / 256, 256>>>(W2, rW, b2, rroot, nroot);
    fc_kernel<<<(NN + WPB - 1) / WPB, WPB * 32>>>(x, fcW, fcb);

    for (int l = 0; l < NLAY; l++) {
        int p = l & 1;
        gemm_mma_kernel<<<dim3((NN + 31) / 32, 6), 256>>>(p, l);
        edge_kernel<<<(NN + WPB - 1) / WPB, WPB * 32>>>();
        combine_kernel<<<(NN * 32 + 255) / 256, 256>>>(
            p, rbias + (size_t)l * 32, nbias + (size_t)l * 32,
            (l == NLAY - 1) ? out : nullptr);
    }
}

// round 8
// speedup vs baseline: 2.1718x; 1.0392x over previous
#include <cuda_runtime.h>
#include <cuda_fp16.h>
#include <cstdint>

#define NN    50000
#define EE    400000
#define NREL  8
#define NLAY  5
#define WPB   8            // warps per block (256 threads)
#define NCOL  1536         // GEMM N: 1024 G | 256 Xr | 64 B | 64 roots | pad
#define H2N   768          // half2 per node row of g_Gh

typedef unsigned int u32;

// ---------------- scratch (static device globals; no allocations) ----------
__device__ __half   g_WcatH[NLAY][NCOL * 32];    // fused fp16 weights, col-major [j][i]
__device__ __half2  g_Gh[(size_t)NN * H2N];      // 153 MB: per-node G|Xr|B|roots fp16
__device__ float    g_h[2][NN * 32];
__device__ float    g_invrel[NREL][NN];
__device__ int      g_counter[2];
__device__ int      g_outdeg[NN];
__device__ int      g_indeg[NN];
__device__ int      g_cursor[NN];
__device__ int      g_incur[NN];
__device__ int      g_rowptr[NN];
__device__ int      g_inrow[NN];
__device__ int      g_ceid[EE];
__device__ int      g_inlist[EE];                // dst-CSR: src-major positions
__device__ int2     g_erec2[EE];                 // {r, wr_bits}
__device__ u32      g_chid2[(size_t)EE * 16];    // per-edge hidden, half2 pairs
__device__ u32      g_msg2[(size_t)EE * 32];     // per-edge half2(mm, dv), 51 MB

__device__ __forceinline__ u32 pack_h2(float a, float b) {
    __half2 h = __floats2half2_rn(a, b);
    return *(u32*)&h;
}

// ---------------- init / counts ----------------------------------------------
__global__ void init_kernel() {
    int i = blockIdx.x * blockDim.x + threadIdx.x;
    if (i < 2) g_counter[i] = 0;
    if (i < NN) { g_outdeg[i] = 0; g_indeg[i] = 0; }
    if (i < NN * NREL) ((float*)g_invrel)[i] = 0.f;
}

__global__ void count_kernel(const int* __restrict__ src,
                             const int* __restrict__ dst,
                             const int* __restrict__ etype) {
    int e = blockIdx.x * blockDim.x + threadIdx.x;
    if (e >= EE) return;
    int d = dst[e], r = etype[e];
    atomicAdd(&g_indeg[d], 1);
    atomicAdd(&g_invrel[r][d], 1.f);
    atomicAdd(&g_outdeg[src[e]], 1);
}

__global__ void invert_kernel() {
    int i = blockIdx.x * blockDim.x + threadIdx.x;
    if (i < NN * NREL) {
        float v = ((float*)g_invrel)[i];
        ((float*)g_invrel)[i] = 1.f / fmaxf(v, 1.f);
    }
}

__global__ void assign_kernel() {
    int i = blockIdx.x * blockDim.x + threadIdx.x;
    if (i >= NN) return;
    g_rowptr[i] = atomicAdd(&g_counter[0], g_outdeg[i]);
    g_inrow[i]  = atomicAdd(&g_counter[1], g_indeg[i]);
    g_cursor[i] = 0;
    g_incur[i]  = 0;
}

__global__ void fill_kernel(const int* __restrict__ src,
                            const int* __restrict__ dst,
                            const int* __restrict__ etype) {
    int e = blockIdx.x * blockDim.x + threadIdx.x;
    if (e >= EE) return;
    int s = src[e], d = dst[e], r = etype[e];
    int pos = g_rowptr[s] + atomicAdd(&g_cursor[s], 1);
    g_ceid[pos] = e;
    int2 rec;
    rec.x = r;
    rec.y = __float_as_int(g_invrel[r][d]);
    g_erec2[pos] = rec;
    int pin = g_inrow[d] + atomicAdd(&g_incur[d], 1);
    g_inlist[pin] = pos;
}

// per-edge hidden (layer-invariant), packed half2 over k-pairs
__global__ __launch_bounds__(WPB * 32) void hid_kernel(
    const int* __restrict__ etype, const float* __restrict__ edist,
    const float* __restrict__ W1, const float* __restrict__ b1) {
    int warp = threadIdx.x >> 5, lane = threadIdx.x & 31;
    int pos = blockIdx.x * WPB + warp;
    if (pos >= EE) return;
    int e = g_ceid[pos];
    int r = etype[e];
    float dd = edist[e];
    float h = fmaxf(dd * W1[lane] + W1[(1 + r) * 32 + lane] + b1[lane], 0.f);
    float hlo = __shfl_sync(0xffffffffu, h, 2 * (lane & 15));
    float hhi = __shfl_sync(0xffffffffu, h, 2 * (lane & 15) + 1);
    if (lane < 16)
        g_chid2[(size_t)pos * 16 + lane] = pack_h2(hlo, hhi);
}

// ---------------- build fused fp16 weight matrix, col-major [j][i] -----------
__global__ void wcat_kernel(const float* __restrict__ W2,
                            const float* __restrict__ rW,
                            const float* __restrict__ b2,
                            const float* __restrict__ rroot,
                            const float* __restrict__ nroot) {
    int idx = blockIdx.x * blockDim.x + threadIdx.x;
    if (idx >= NLAY * NCOL * 32) return;
    int l = idx / (NCOL * 32);
    int rem = idx % (NCOL * 32);
    int j = rem >> 5, i = rem & 31;
    int p = j >> 1, par = j & 1;
    float v = 0.f;
    if (p < 512) {
        int k = 2 * (p >> 5) + par, o = p & 31;
        v = W2[k * 1024 + i * 32 + o];
    } else if (p < 640) {
        int r = 2 * ((p - 512) >> 5) + par, o = p & 31;
        v = rW[(((size_t)l * NREL + r) * 32 + i) * 32 + o];
    } else if (p < 672) {
        if (par == 0) v = b2[i * 32 + (p - 640)];
    } else if (p < 704) {
        int o = p - 672;
        v = par ? nroot[((size_t)l * 32 + i) * 32 + o]
                : rroot[((size_t)l * 32 + i) * 32 + o];
    }
    g_WcatH[l][rem] = __float2half(v);
}

// ---------------- h0 = relu(x @ fc_W + fc_b) --------------------------------
__global__ __launch_bounds__(WPB * 32) void fc_kernel(
    const float* __restrict__ x, const float* __restrict__ W,
    const float* __restrict__ b) {
    int warp = threadIdx.x >> 5, lane = threadIdx.x & 31;
    int n = blockIdx.x * WPB + warp;
    if (n >= NN) return;
    float xv = x[n * 32 + lane];
    float acc = b[lane];
#pragma unroll
    for (int k = 0; k < 32; k++)
        acc = fmaf(__shfl_sync(0xffffffffu, xv, k), W[k * 32 + lane], acc);
    g_h[0][n * 32 + lane] = fmaxf(acc, 0.f);
}

// ---------------- tensor-core GEMM: Gh = h @ WcatH --------------------------
__global__ __launch_bounds__(256) void gemm_mma_kernel(int p, int l) {
    __shared__ __half2 sOut[32][132];
    int t = threadIdx.x, warp = t >> 5, lane = t & 31;
    int wm = warp >> 2, wn = warp & 3;
    int nblk = blockIdx.x * 32;
    int by = blockIdx.y;
    int m0 = wm * 16;
    int g = lane >> 2, tq = lane & 3;
    const __half* Wl = g_WcatH[l];
    const float* hp = g_h[p];

    float acc[8][4];
#pragma unroll
    for (int nt = 0; nt < 8; nt++)
#pragma unroll
        for (int c = 0; c < 4; c++) acc[nt][c] = 0.f;

    int nodeA = nblk + m0 + g;
    int nodeB = nodeA + 8;
    bool vA = nodeA < NN, vB = nodeB < NN;

#pragma unroll
    for (int kk = 0; kk < 2; kk++) {
        int kb = kk * 16 + tq * 2;
        float2 f00 = vA ? *(const float2*)&hp[(size_t)nodeA * 32 + kb]
                        : make_float2(0.f, 0.f);
        float2 f01 = vA ? *(const float2*)&hp[(size_t)nodeA * 32 + kb + 8]
                        : make_float2(0.f, 0.f);
        float2 f10 = vB ? *(const float2*)&hp[(size_t)nodeB * 32 + kb]
                        : make_float2(0.f, 0.f);
        float2 f11 = vB ? *(const float2*)&hp[(size_t)nodeB * 32 + kb + 8]
                        : make_float2(0.f, 0.f);
        u32 a0 = pack_h2(f00.x, f00.y);
        u32 a1 = pack_h2(f10.x, f10.y);
        u32 a2 = pack_h2(f01.x, f01.y);
        u32 a3 = pack_h2(f11.x, f11.y);
#pragma unroll
        for (int nt = 0; nt < 8; nt++) {
            int j = by * 256 + wn * 64 + nt * 8 + g;
            u32 b0 = *(const u32*)&Wl[j * 32 + kk * 16 + tq * 2];
            u32 b1 = *(const u32*)&Wl[j * 32 + kk * 16 + tq * 2 + 8];
            asm("mma.sync.aligned.m16n8k16.row.col.f32.f16.f16.f32 "
                "{%0,%1,%2,%3}, {%4,%5,%6,%7}, {%8,%9}, {%0,%1,%2,%3};"
                : "+f"(acc[nt][0]), "+f"(acc[nt][1]),
                  "+f"(acc[nt][2]), "+f"(acc[nt][3])
                : "r"(a0), "r"(a1), "r"(a2), "r"(a3), "r"(b0), "r"(b1));
        }
    }

#pragma unroll
    for (int nt = 0; nt < 8; nt++) {
        int pl = wn * 32 + nt * 4 + tq;
        sOut[m0 + g][pl]     = __floats2half2_rn(acc[nt][0], acc[nt][1]);
        sOut[m0 + 8 + g][pl] = __floats2half2_rn(acc[nt][2], acc[nt][3]);
    }
    __syncthreads();

    int row = t >> 3, seg = t & 7;
    int node = nblk + row;
    if (node < NN) {
        __half2* dst = &g_Gh[(size_t)node * H2N + by * 128];
#pragma unroll
        for (int it = 0; it < 2; it++) {
            uint4 v  = *(uint4*)&sOut[row][seg * 16 + it * 8];
            uint4 v2 = *(uint4*)&sOut[row][seg * 16 + it * 8 + 4];
            *(uint4*)&dst[seg * 16 + it * 8]     = v;
            *(uint4*)&dst[seg * 16 + it * 8 + 4] = v2;
        }
    }
}

// ---------------- per-layer message kernel (warp per source) ----------------
__global__ __launch_bounds__(256) void msg_kernel() {
    __shared__ float sXr[WPB][NREL][32];     // 8 KB
    int t = threadIdx.x, warp = t >> 5, lane = t & 31;
    int n = blockIdx.x * WPB + warp;
    if (n >= NN) return;

    const __half2* gr = &g_Gh[(size_t)n * H2N];
    __half2 G2[16];
#pragma unroll
    for (int k2 = 0; k2 < 16; k2++) G2[k2] = gr[k2 * 32 + lane];
#pragma unroll
    for (int c2 = 0; c2 < 4; c2++) {
        float2 xp = __half22float2(gr[(16 + c2) * 32 + lane]);
        sXr[warp][2 * c2][lane]     = xp.x;
        sXr[warp][2 * c2 + 1][lane] = xp.y;
    }
    float B = __low2float(gr[640 + lane]);
    __syncwarp();

    int beg = g_rowptr[n], end = beg + g_outdeg[n];
    int pos = beg;
    for (; pos + 2 <= end; pos += 2) {
        int2 eA = g_erec2[pos], eB = g_erec2[pos + 1];
        u32 myh = g_chid2[(size_t)pos * 16 + lane];  // lanes 0-15: A, 16-31: B
        __half2 accA = __float2half2_rn(0.f), accB = accA;
#pragma unroll
        for (int k2 = 0; k2 < 16; k2++) {
            u32 ha = __shfl_sync(0xffffffffu, myh, k2);
            u32 hb = __shfl_sync(0xffffffffu, myh, 16 + k2);
            accA = __hfma2(*(__half2*)&ha, G2[k2], accA);
            accB = __hfma2(*(__half2*)&hb, G2[k2], accB);
        }
        float2 fA = __half22float2(accA), fB = __half22float2(accB);
        float mmA = fA.x + fA.y + B;
        float mmB = fB.x + fB.y + B;
        float dvA = sXr[warp][eA.x][lane] * __int_as_float(eA.y);
        float dvB = sXr[warp][eB.x][lane] * __int_as_float(eB.y);
        g_msg2[(size_t)pos * 32 + lane]       = pack_h2(mmA, dvA);
        g_msg2[(size_t)(pos + 1) * 32 + lane] = pack_h2(mmB, dvB);
    }
    if (pos < end) {   // tail single edge
        int2 eA = g_erec2[pos];
        u32 myh = g_chid2[(size_t)pos * 16 + (lane & 15)];
        __half2 accA = __float2half2_rn(0.f);
#pragma unroll
        for (int k2 = 0; k2 < 16; k2++) {
            u32 ha = __shfl_sync(0xffffffffu, myh, k2);
            accA = __hfma2(*(__half2*)&ha, G2[k2], accA);
        }
        float2 fA = __half22float2(accA);
        float mmA = fA.x + fA.y + B;
        float dvA = sXr[warp][eA.x][lane] * __int_as_float(eA.y);
        g_msg2[(size_t)pos * 32 + lane] = pack_h2(mmA, dvA);
    }
}

// ---------------- per-layer gather + combine (warp per destination) ---------
__global__ __launch_bounds__(256) void gather_kernel(
    int p, const float* __restrict__ rbias, const float* __restrict__ nbias,
    float* __restrict__ out_final) {
    int t = threadIdx.x, warp = t >> 5, lane = t & 31;
    int n = blockIdx.x * WPB + warp;
    if (n >= NN) return;

    int beg = g_inrow[n], cnt = g_indeg[n];
    float mms = 0.f, dvs = 0.f;
    int j = 0;
    for (; j + 4 <= cnt; j += 4) {
        int p0 = g_inlist[beg + j + 0];
        int p1 = g_inlist[beg + j + 1];
        int p2 = g_inlist[beg + j + 2];
        int p3 = g_inlist[beg + j + 3];
        u32 v0 = g_msg2[(size_t)p0 * 32 + lane];
        u32 v1 = g_msg2[(size_t)p1 * 32 + lane];
        u32 v2 = g_msg2[(size_t)p2 * 32 + lane];
        u32 v3 = g_msg2[(size_t)p3 * 32 + lane];
        float2 f0 = __half22float2(*(__half2*)&v0);
        float2 f1 = __half22float2(*(__half2*)&v1);
        float2 f2 = __half22float2(*(__half2*)&v2);
        float2 f3 = __half22float2(*(__half2*)&v3);
        mms += (f0.x + f1.x) + (f2.x + f3.x);
        dvs += (f0.y + f1.y) + (f2.y + f3.y);
    }
    for (; j < cnt; j++) {
        int pi = g_inlist[beg + j];
        u32 v = g_msg2[(size_t)pi * 32 + lane];
        float2 f = __half22float2(*(__half2*)&v);
        mms += f.x;
        dvs += f.y;
    }
    float invd = 1.f / fmaxf((float)cnt, 1.f);

    size_t idx = (size_t)n * 32 + lane;
    float2 roots = __half22float2(g_Gh[(size_t)n * H2N + 672 + lane]);
    float hv = g_h[p][idx];
    float v = hv + fmaxf(roots.x + rbias[lane] + dvs, 0.f)
                 + fmaxf(roots.y + nbias[lane] + mms * invd, 0.f);
    if (out_final) out_final[idx] = v;
    else           g_h[p ^ 1][idx] = v;
}

// ---------------- host launch ------------------------------------------------
extern "C" void kernel_launch(void* const* d_in, const int* in_sizes, int n_in,
                              void* d_out, int out_size) {
    const float* x     = (const float*)d_in[0];
    const int*   eidx  = (const int*)  d_in[1];   // [2,E]: src then dst
    const int*   etype = (const int*)  d_in[2];
    const float* edist = (const float*)d_in[3];
    const float* fcW   = (const float*)d_in[4];
    const float* fcb   = (const float*)d_in[5];
    const float* rW    = (const float*)d_in[6];   // [L,R,32,32]
    const float* rroot = (const float*)d_in[7];   // [L,32,32]
    const float* rbias = (const float*)d_in[8];   // [L,32]
    const float* W1    = (const float*)d_in[9];   // [9,32]
    const float* b1    = (const float*)d_in[10];  // [32]
    const float* W2    = (const float*)d_in[11];  // [32,1024]
    const float* b2    = (const float*)d_in[12];  // [1024]
    const float* nroot = (const float*)d_in[13];  // [L,32,32]
    const float* nbias = (const float*)d_in[14];  // [L,32]
    float* out = (float*)d_out;

    const int* srcp = eidx;
    const int* dstp = eidx + EE;

    init_kernel<<<(NN * NREL + 255) / 256, 256>>>();
    count_kernel<<<(EE + 255) / 256, 256>>>(srcp, dstp, etype);
    invert_kernel<<<(NN * NREL + 255) / 256, 256>>>();
    assign_kernel<<<(NN + 255) / 256, 256>>>();
    fill_kernel<<<(EE + 255) / 256, 256>>>(srcp, dstp, etype);
    hid_kernel<<<(EE + WPB - 1) / WPB, WPB * 32>>>(etype, edist, W1, b1);
    wcat_kernel<<<(NLAY * NCOL * 32 + 255) / 256, 256>>>(W2, rW, b2, rroot, nroot);
    fc_kernel<<<(NN + WPB - 1) / WPB, WPB * 32>>>(x, fcW, fcb);

    for (int l = 0; l < NLAY; l++) {
        int p = l & 1;
        gemm_mma_kernel<<<dim3((NN + 31) / 32, 6), 256>>>(p, l);
        msg_kernel<<<(NN + WPB - 1) / WPB, WPB * 32>>>();
        gather_kernel<<<(NN + WPB - 1) / WPB, WPB * 32>>>(
            p, rbias + (size_t)l * 32, nbias + (size_t)l * 32,
            (l == NLAY - 1) ? out : nullptr);
    }
}

// round 9
// speedup vs baseline: 2.3276x; 1.0717x over previous
#include <cuda_runtime.h>
#include <cuda_fp16.h>
#include <cstdint>

#define NN    50000
#define EE    400000
#define NREL  8
#define NLAY  5
#define WPB   8            // warps per block (256 threads)
#define NCOL  1536         // GEMM N: 1024 G | 256 Xr | 64 B | 64 roots | pad
#define SROW  772          // smem row stride in half2 (bank-conflict-free)

typedef unsigned int u32;

// ---------------- scratch (static device globals; no allocations) ----------
__device__ __half   g_WcatH[NLAY][NCOL * 32];    // fused fp16 weights, col-major [j][i]
__device__ __half2  g_roots[NN * 32];            // per-node (rroot,nroot) pairs
__device__ float    g_h[2][NN * 32];
__device__ float    g_invrel[NREL][NN];
__device__ int      g_counter[2];
__device__ int      g_outdeg[NN];
__device__ int      g_indeg[NN];
__device__ int      g_cursor[NN];
__device__ int      g_incur[NN];
__device__ int      g_rowptr[NN];
__device__ int      g_inrow[NN];
__device__ int      g_ceid[EE];
__device__ int      g_inlist[EE];                // dst-CSR: src-major positions
__device__ int2     g_erec2[EE];                 // {r, wr_bits}
__device__ u32      g_chid2[(size_t)EE * 16];    // per-edge hidden, half2 pairs
__device__ u32      g_msg2[(size_t)EE * 32];     // per-edge half2(mm, dv), 51 MB

__device__ __forceinline__ u32 pack_h2(float a, float b) {
    __half2 h = __floats2half2_rn(a, b);
    return *(u32*)&h;
}

// ---------------- init / counts ----------------------------------------------
__global__ void init_kernel() {
    int i = blockIdx.x * blockDim.x + threadIdx.x;
    if (i < 2) g_counter[i] = 0;
    if (i < NN) { g_outdeg[i] = 0; g_indeg[i] = 0; }
    if (i < NN * NREL) ((float*)g_invrel)[i] = 0.f;
}

__global__ void count_kernel(const int* __restrict__ src,
                             const int* __restrict__ dst,
                             const int* __restrict__ etype) {
    int e = blockIdx.x * blockDim.x + threadIdx.x;
    if (e >= EE) return;
    int d = dst[e], r = etype[e];
    atomicAdd(&g_indeg[d], 1);
    atomicAdd(&g_invrel[r][d], 1.f);
    atomicAdd(&g_outdeg[src[e]], 1);
}

__global__ void invert_kernel() {
    int i = blockIdx.x * blockDim.x + threadIdx.x;
    if (i < NN * NREL) {
        float v = ((float*)g_invrel)[i];
        ((float*)g_invrel)[i] = 1.f / fmaxf(v, 1.f);
    }
}

__global__ void assign_kernel() {
    int i = blockIdx.x * blockDim.x + threadIdx.x;
    if (i >= NN) return;
    g_rowptr[i] = atomicAdd(&g_counter[0], g_outdeg[i]);
    g_inrow[i]  = atomicAdd(&g_counter[1], g_indeg[i]);
    g_cursor[i] = 0;
    g_incur[i]  = 0;
}

__global__ void fill_kernel(const int* __restrict__ src,
                            const int* __restrict__ dst,
                            const int* __restrict__ etype) {
    int e = blockIdx.x * blockDim.x + threadIdx.x;
    if (e >= EE) return;
    int s = src[e], d = dst[e], r = etype[e];
    int pos = g_rowptr[s] + atomicAdd(&g_cursor[s], 1);
    g_ceid[pos] = e;
    int2 rec;
    rec.x = r;
    rec.y = __float_as_int(g_invrel[r][d]);
    g_erec2[pos] = rec;
    int pin = g_inrow[d] + atomicAdd(&g_incur[d], 1);
    g_inlist[pin] = pos;
}

// per-edge hidden (layer-invariant), packed half2 over k-pairs
__global__ __launch_bounds__(WPB * 32) void hid_kernel(
    const int* __restrict__ etype, const float* __restrict__ edist,
    const float* __restrict__ W1, const float* __restrict__ b1) {
    int warp = threadIdx.x >> 5, lane = threadIdx.x & 31;
    int pos = blockIdx.x * WPB + warp;
    if (pos >= EE) return;
    int e = g_ceid[pos];
    int r = etype[e];
    float dd = edist[e];
    float h = fmaxf(dd * W1[lane] + W1[(1 + r) * 32 + lane] + b1[lane], 0.f);
    float hlo = __shfl_sync(0xffffffffu, h, 2 * (lane & 15));
    float hhi = __shfl_sync(0xffffffffu, h, 2 * (lane & 15) + 1);
    if (lane < 16)
        g_chid2[(size_t)pos * 16 + lane] = pack_h2(hlo, hhi);
}

// ---------------- build fused fp16 weight matrix, col-major [j][i] -----------
__global__ void wcat_kernel(const float* __restrict__ W2,
                            const float* __restrict__ rW,
                            const float* __restrict__ b2,
                            const float* __restrict__ rroot,
                            const float* __restrict__ nroot) {
    int idx = blockIdx.x * blockDim.x + threadIdx.x;
    if (idx >= NLAY * NCOL * 32) return;
    int l = idx / (NCOL * 32);
    int rem = idx % (NCOL * 32);
    int j = rem >> 5, i = rem & 31;
    int p = j >> 1, par = j & 1;
    float v = 0.f;
    if (p < 512) {
        int k = 2 * (p >> 5) + par, o = p & 31;
        v = W2[k * 1024 + i * 32 + o];
    } else if (p < 640) {
        int r = 2 * ((p - 512) >> 5) + par, o = p & 31;
        v = rW[(((size_t)l * NREL + r) * 32 + i) * 32 + o];
    } else if (p < 672) {
        if (par == 0) v = b2[i * 32 + (p - 640)];
    } else if (p < 704) {
        int o = p - 672;
        v = par ? nroot[((size_t)l * 32 + i) * 32 + o]
                : rroot[((size_t)l * 32 + i) * 32 + o];
    }
    g_WcatH[l][rem] = __float2half(v);
}

// ---------------- h0 = relu(x @ fc_W + fc_b) --------------------------------
__global__ __launch_bounds__(WPB * 32) void fc_kernel(
    const float* __restrict__ x, const float* __restrict__ W,
    const float* __restrict__ b) {
    int warp = threadIdx.x >> 5, lane = threadIdx.x & 31;
    int n = blockIdx.x * WPB + warp;
    if (n >= NN) return;
    float xv = x[n * 32 + lane];
    float acc = b[lane];
#pragma unroll
    for (int k = 0; k < 32; k++)
        acc = fmaf(__shfl_sync(0xffffffffu, xv, k), W[k * 32 + lane], acc);
    g_h[0][n * 32 + lane] = fmaxf(acc, 0.f);
}

// ---------------- fused GEMM(mma) + message kernel ---------------------------
// Block = 32 nodes. Phase 1: Gcat = h @ WcatH -> smem (96.5 KB).
// Phase 2: warp walks 4 nodes' CSR edges, G from smem/regs, msg -> global.
__global__ __launch_bounds__(256) void fusedmsg_kernel(int p, int l) {
    extern __shared__ __half2 sG[];        // [32][SROW]
    int t = threadIdx.x, warp = t >> 5, lane = t & 31;
    int wm = warp >> 2, wn = warp & 3;
    int nblk = blockIdx.x * 32;
    int m0 = wm * 16;
    int g = lane >> 2, tq = lane & 3;
    const __half* Wl = g_WcatH[l];
    const float* hp = g_h[p];

    // ---- load A fragments once ----
    int nodeA = nblk + m0 + g;
    int nodeB = nodeA + 8;
    bool vA = nodeA < NN, vB = nodeB < NN;
    u32 afrag[2][4];
#pragma unroll
    for (int kk = 0; kk < 2; kk++) {
        int kb = kk * 16 + tq * 2;
        float2 f00 = vA ? *(const float2*)&hp[(size_t)nodeA * 32 + kb]
                        : make_float2(0.f, 0.f);
        float2 f01 = vA ? *(const float2*)&hp[(size_t)nodeA * 32 + kb + 8]
                        : make_float2(0.f, 0.f);
        float2 f10 = vB ? *(const float2*)&hp[(size_t)nodeB * 32 + kb]
                        : make_float2(0.f, 0.f);
        float2 f11 = vB ? *(const float2*)&hp[(size_t)nodeB * 32 + kb + 8]
                        : make_float2(0.f, 0.f);
        afrag[kk][0] = pack_h2(f00.x, f00.y);
        afrag[kk][1] = pack_h2(f10.x, f10.y);
        afrag[kk][2] = pack_h2(f01.x, f01.y);
        afrag[kk][3] = pack_h2(f11.x, f11.y);
    }

    // ---- phase 1: 6 chunks of 256 cols ----
#pragma unroll
    for (int by = 0; by < 6; by++) {
        float acc[8][4];
#pragma unroll
        for (int nt = 0; nt < 8; nt++)
#pragma unroll
            for (int c = 0; c < 4; c++) acc[nt][c] = 0.f;
#pragma unroll
        for (int kk = 0; kk < 2; kk++) {
#pragma unroll
            for (int nt = 0; nt < 8; nt++) {
                int j = by * 256 + wn * 64 + nt * 8 + g;
                u32 b0 = *(const u32*)&Wl[j * 32 + kk * 16 + tq * 2];
                u32 b1 = *(const u32*)&Wl[j * 32 + kk * 16 + tq * 2 + 8];
                asm("mma.sync.aligned.m16n8k16.row.col.f32.f16.f16.f32 "
                    "{%0,%1,%2,%3}, {%4,%5,%6,%7}, {%8,%9}, {%0,%1,%2,%3};"
                    : "+f"(acc[nt][0]), "+f"(acc[nt][1]),
                      "+f"(acc[nt][2]), "+f"(acc[nt][3])
                    : "r"(afrag[kk][0]), "r"(afrag[kk][1]),
                      "r"(afrag[kk][2]), "r"(afrag[kk][3]),
                      "r"(b0), "r"(b1));
            }
        }
#pragma unroll
        for (int nt = 0; nt < 8; nt++) {
            int pl = by * 128 + wn * 32 + nt * 4 + tq;
            sG[(m0 + g) * SROW + pl]     = __floats2half2_rn(acc[nt][0], acc[nt][1]);
            sG[(m0 + 8 + g) * SROW + pl] = __floats2half2_rn(acc[nt][2], acc[nt][3]);
        }
    }
    __syncthreads();

    // ---- export roots (pairs 672..703) ----
#pragma unroll
    for (int it = 0; it < 4; it++) {
        int id = it * 256 + t;
        int node = id >> 5, o = id & 31;
        if (nblk + node < NN)
            g_roots[(size_t)(nblk + node) * 32 + o] = sG[node * SROW + 672 + o];
    }

    // ---- phase 2: edges (warp handles 4 nodes) ----
    for (int nn = 0; nn < 4; nn++) {
        int node = warp + nn * 8;
        int n = nblk + node;
        if (n >= NN) break;
        const __half2* gnode = &sG[node * SROW];
        __half2 G2[16];
#pragma unroll
        for (int k2 = 0; k2 < 16; k2++) G2[k2] = gnode[k2 * 32 + lane];
        float B = __low2float(gnode[640 + lane]);

        int beg = g_rowptr[n], end = beg + g_outdeg[n];
        int pos = beg;
        for (; pos + 2 <= end; pos += 2) {
            int2 eA = g_erec2[pos], eB = g_erec2[pos + 1];
            u32 myh = g_chid2[(size_t)pos * 16 + lane]; // lanes 0-15: A, 16-31: B
            __half2 accA = __float2half2_rn(0.f), accB = accA;
#pragma unroll
            for (int k2 = 0; k2 < 16; k2++) {
                u32 ha = __shfl_sync(0xffffffffu, myh, k2);
                u32 hb = __shfl_sync(0xffffffffu, myh, 16 + k2);
                accA = __hfma2(*(__half2*)&ha, G2[k2], accA);
                accB = __hfma2(*(__half2*)&hb, G2[k2], accB);
            }
            float2 fA = __half22float2(accA), fB = __half22float2(accB);
            float mmA = fA.x + fA.y + B;
            float mmB = fB.x + fB.y + B;
            __half2 xpA = gnode[512 + (eA.x >> 1) * 32 + lane];
            __half2 xpB = gnode[512 + (eB.x >> 1) * 32 + lane];
            float xrA = (eA.x & 1) ? __high2float(xpA) : __low2float(xpA);
            float xrB = (eB.x & 1) ? __high2float(xpB) : __low2float(xpB);
            float dvA = xrA * __int_as_float(eA.y);
            float dvB = xrB * __int_as_float(eB.y);
            g_msg2[(size_t)pos * 32 + lane]       = pack_h2(mmA, dvA);
            g_msg2[(size_t)(pos + 1) * 32 + lane] = pack_h2(mmB, dvB);
        }
        if (pos < end) {   // tail single edge
            int2 eA = g_erec2[pos];
            u32 myh = g_chid2[(size_t)pos * 16 + (lane & 15)];
            __half2 accA = __float2half2_rn(0.f);
#pragma unroll
            for (int k2 = 0; k2 < 16; k2++) {
                u32 ha = __shfl_sync(0xffffffffu, myh, k2);
                accA = __hfma2(*(__half2*)&ha, G2[k2], accA);
            }
            float2 fA = __half22float2(accA);
            float mmA = fA.x + fA.y + B;
            __half2 xpA = gnode[512 + (eA.x >> 1) * 32 + lane];
            float xrA = (eA.x & 1) ? __high2float(xpA) : __low2float(xpA);
            float dvA = xrA * __int_as_float(eA.y);
            g_msg2[(size_t)pos * 32 + lane] = pack_h2(mmA, dvA);
        }
    }
}

// ---------------- per-layer gather + combine (warp per destination) ---------
__global__ __launch_bounds__(256) void gather_kernel(
    int p, const float* __restrict__ rbias, const float* __restrict__ nbias,
    float* __restrict__ out_final) {
    int t = threadIdx.x, warp = t >> 5, lane = t & 31;
    int n = blockIdx.x * WPB + warp;
    if (n >= NN) return;

    int beg = g_inrow[n], cnt = g_indeg[n];
    float mms = 0.f, dvs = 0.f;
    int j = 0;
    for (; j + 4 <= cnt; j += 4) {
        int p0 = g_inlist[beg + j + 0];
        int p1 = g_inlist[beg + j + 1];
        int p2 = g_inlist[beg + j + 2];
        int p3 = g_inlist[beg + j + 3];
        u32 v0 = g_msg2[(size_t)p0 * 32 + lane];
        u32 v1 = g_msg2[(size_t)p1 * 32 + lane];
        u32 v2 = g_msg2[(size_t)p2 * 32 + lane];
        u32 v3 = g_msg2[(size_t)p3 * 32 + lane];
        float2 f0 = __half22float2(*(__half2*)&v0);
        float2 f1 = __half22float2(*(__half2*)&v1);
        float2 f2 = __half22float2(*(__half2*)&v2);
        float2 f3 = __half22float2(*(__half2*)&v3);
        mms += (f0.x + f1.x) + (f2.x + f3.x);
        dvs += (f0.y + f1.y) + (f2.y + f3.y);
    }
    for (; j < cnt; j++) {
        int pi = g_inlist[beg + j];
        u32 v = g_msg2[(size_t)pi * 32 + lane];
        float2 f = __half22float2(*(__half2*)&v);
        mms += f.x;
        dvs += f.y;
    }
    float invd = 1.f / fmaxf((float)cnt, 1.f);

    size_t idx = (size_t)n * 32 + lane;
    float2 roots = __half22float2(g_roots[idx]);
    float hv = g_h[p][idx];
    float v = hv + fmaxf(roots.x + rbias[lane] + dvs, 0.f)
                 + fmaxf(roots.y + nbias[lane] + mms * invd, 0.f);
    if (out_final) out_final[idx] = v;
    else           g_h[p ^ 1][idx] = v;
}

// ---------------- host launch ------------------------------------------------
extern "C" void kernel_launch(void* const* d_in, const int* in_sizes, int n_in,
                              void* d_out, int out_size) {
    const float* x     = (const float*)d_in[0];
    const int*   eidx  = (const int*)  d_in[1];   // [2,E]: src then dst
    const int*   etype = (const int*)  d_in[2];
    const float* edist = (const float*)d_in[3];
    const float* fcW   = (const float*)d_in[4];
    const float* fcb   = (const float*)d_in[5];
    const float* rW    = (const float*)d_in[6];   // [L,R,32,32]
    const float* rroot = (const float*)d_in[7];   // [L,32,32]
    const float* rbias = (const float*)d_in[8];   // [L,32]
    const float* W1    = (const float*)d_in[9];   // [9,32]
    const float* b1    = (const float*)d_in[10];  // [32]
    const float* W2    = (const float*)d_in[11];  // [32,1024]
    const float* b2    = (const float*)d_in[12];  // [1024]
    const float* nroot = (const float*)d_in[13];  // [L,32,32]
    const float* nbias = (const float*)d_in[14];  // [L,32]
    float* out = (float*)d_out;

    const int* srcp = eidx;
    const int* dstp = eidx + EE;

    int smem = 32 * SROW * 4;  // 98816 bytes
    cudaFuncSetAttribute(fusedmsg_kernel,
                         cudaFuncAttributeMaxDynamicSharedMemorySize, smem);

    init_kernel<<<(NN * NREL + 255) / 256, 256>>>();
    count_kernel<<<(EE + 255) / 256, 256>>>(srcp, dstp, etype);
    invert_kernel<<<(NN * NREL + 255) / 256, 256>>>();
    assign_kernel<<<(NN + 255) / 256, 256>>>();
    fill_kernel<<<(EE + 255) / 256, 256>>>(srcp, dstp, etype);
    hid_kernel<<<(EE + WPB - 1) / WPB, WPB * 32>>>(etype, edist, W1, b1);
    wcat_kernel<<<(NLAY * NCOL * 32 + 255) / 256, 256>>>(W2, rW, b2, rroot, nroot);
    fc_kernel<<<(NN + WPB - 1) / WPB, WPB * 32>>>(x, fcW, fcb);

    for (int l = 0; l < NLAY; l++) {
        int p = l & 1;
        fusedmsg_kernel<<<(NN + 31) / 32, 256, smem>>>(p, l);
        gather_kernel<<<(NN + WPB - 1) / WPB, WPB * 32>>>(
            p, rbias + (size_t)l * 32, nbias + (size_t)l * 32,
            (l == NLAY - 1) ? out : nullptr);
    }
}

// round 10
// speedup vs baseline: 3.6228x; 1.5565x over previous
#include <cuda_runtime.h>
#include <cuda_fp16.h>
#include <cstdint>

#define NN    50000
#define EE    400000
#define NREL  8
#define NLAY  5
#define WPB   8            // warps per block (gather)
#define NCOL  1536         // GEMM N: 1024 G | 256 Xr | 64 B | 64 roots | pad
#define SROW  772          // smem row stride in half2 (bank-conflict-free)

typedef unsigned int u32;

// ---------------- scratch (static device globals; no allocations) ----------
__device__ __half   g_WcatH[NLAY][NCOL * 32];    // fused fp16 weights, col-major [j][i]
__device__ __half2  g_roots[NN * 32];            // per-node (rroot,nroot) pairs
__device__ float    g_h[2][NN * 32];
__device__ float    g_invrel[NREL][NN];
__device__ int      g_counter[2];
__device__ int      g_outdeg[NN];
__device__ int      g_indeg[NN];
__device__ int      g_cursor[NN];
__device__ int      g_incur[NN];
__device__ int      g_rowptr[NN];
__device__ int      g_inrow[NN];
__device__ int      g_inlist[EE];                // dst-CSR: src-major positions
__device__ int4     g_erec[EE];                  // {r, wr_bits, dist_bits, 0}
__device__ u32      g_msg2[(size_t)EE * 32];     // per-edge half2(mm, dv), 51 MB

__device__ __forceinline__ u32 pack_h2(float a, float b) {
    __half2 h = __floats2half2_rn(a, b);
    return *(u32*)&h;
}

// ---------------- init / counts ----------------------------------------------
__global__ void init_kernel() {
    int i = blockIdx.x * blockDim.x + threadIdx.x;
    if (i < 2) g_counter[i] = 0;
    if (i < NN) { g_outdeg[i] = 0; g_indeg[i] = 0; }
    if (i < NN * NREL) ((float*)g_invrel)[i] = 0.f;
}

__global__ void count_kernel(const int* __restrict__ src,
                             const int* __restrict__ dst,
                             const int* __restrict__ etype) {
    int e = blockIdx.x * blockDim.x + threadIdx.x;
    if (e >= EE) return;
    int d = dst[e], r = etype[e];
    atomicAdd(&g_indeg[d], 1);
    atomicAdd(&g_invrel[r][d], 1.f);
    atomicAdd(&g_outdeg[src[e]], 1);
}

// invert rel counts + assign CSR segments (order-free)
__global__ void assign_kernel() {
    int i = blockIdx.x * blockDim.x + threadIdx.x;
    if (i < NN * NREL) {
        float v = ((float*)g_invrel)[i];
        ((float*)g_invrel)[i] = 1.f / fmaxf(v, 1.f);
    }
    if (i < NN) {
        g_rowptr[i] = atomicAdd(&g_counter[0], g_outdeg[i]);
        g_inrow[i]  = atomicAdd(&g_counter[1], g_indeg[i]);
        g_cursor[i] = 0;
        g_incur[i]  = 0;
    }
}

__global__ void fill_kernel(const int* __restrict__ src,
                            const int* __restrict__ dst,
                            const int* __restrict__ etype,
                            const float* __restrict__ edist) {
    int e = blockIdx.x * blockDim.x + threadIdx.x;
    if (e >= EE) return;
    int s = src[e], d = dst[e], r = etype[e];
    int pos = g_rowptr[s] + atomicAdd(&g_cursor[s], 1);
    int4 rec;
    rec.x = r;
    rec.y = __float_as_int(g_invrel[r][d]);
    rec.z = __float_as_int(edist[e]);
    rec.w = 0;
    g_erec[pos] = rec;
    int pin = g_inrow[d] + atomicAdd(&g_incur[d], 1);
    g_inlist[pin] = pos;
}

// ---------------- build fused fp16 weight matrix, col-major [j][i] -----------
__global__ void wcat_kernel(const float* __restrict__ W2,
                            const float* __restrict__ rW,
                            const float* __restrict__ b2,
                            const float* __restrict__ rroot,
                            const float* __restrict__ nroot) {
    int idx = blockIdx.x * blockDim.x + threadIdx.x;
    if (idx >= NLAY * NCOL * 32) return;
    int l = idx / (NCOL * 32);
    int rem = idx % (NCOL * 32);
    int j = rem >> 5, i = rem & 31;
    int p = j >> 1, par = j & 1;
    float v = 0.f;
    if (p < 512) {
        int k = 2 * (p >> 5) + par, o = p & 31;
        v = W2[k * 1024 + i * 32 + o];
    } else if (p < 640) {
        int r = 2 * ((p - 512) >> 5) + par, o = p & 31;
        v = rW[(((size_t)l * NREL + r) * 32 + i) * 32 + o];
    } else if (p < 672) {
        if (par == 0) v = b2[i * 32 + (p - 640)];
    } else if (p < 704) {
        int o = p - 672;
        v = par ? nroot[((size_t)l * 32 + i) * 32 + o]
                : rroot[((size_t)l * 32 + i) * 32 + o];
    }
    g_WcatH[l][rem] = __float2half(v);
}

// ---------------- h0 = relu(x @ fc_W + fc_b) --------------------------------
__global__ __launch_bounds__(WPB * 32) void fc_kernel(
    const float* __restrict__ x, const float* __restrict__ W,
    const float* __restrict__ b) {
    int warp = threadIdx.x >> 5, lane = threadIdx.x & 31;
    int n = blockIdx.x * WPB + warp;
    if (n >= NN) return;
    float xv = x[n * 32 + lane];
    float acc = b[lane];
#pragma unroll
    for (int k = 0; k < 32; k++)
        acc = fmaf(__shfl_sync(0xffffffffu, xv, k), W[k * 32 + lane], acc);
    g_h[0][n * 32 + lane] = fmaxf(acc, 0.f);
}

// ---------------- fused GEMM(mma) + message kernel ---------------------------
// 512 threads, 32 nodes/block. Phase 1: 16 warps (2m x 8n) tensor GEMM -> smem.
// Phase 2: warp walks 2 nodes' CSR edges, hid computed on the fly.
__global__ __launch_bounds__(512, 2) void fusedmsg_kernel(
    int p, int l, const float* __restrict__ W1, const float* __restrict__ b1) {
    extern __shared__ __half2 sG[];        // [32][SROW], 96.5 KB
    __shared__ float sW1d[32];             // W1[0][k]
    __shared__ float sW1rb[NREL][32];      // W1[1+r][k] + b1[k]
    int t = threadIdx.x, warp = t >> 5, lane = t & 31;
    int wm = warp >> 3, wn = warp & 7;
    int nblk = blockIdx.x * 32;
    int m0 = wm * 16;
    int g = lane >> 2, tq = lane & 3;
    const __half* Wl = g_WcatH[l];
    const float* hp = g_h[p];

    if (t < 32) sW1d[t] = W1[t];
    else if (t < 288) {
        int r = (t - 32) >> 5, k = t & 31;
        sW1rb[r][k] = W1[(1 + r) * 32 + k] + b1[k];
    }

    // ---- load A fragments once ----
    int nodeA = nblk + m0 + g;
    int nodeB = nodeA + 8;
    bool vA = nodeA < NN, vB = nodeB < NN;
    u32 afrag[2][4];
#pragma unroll
    for (int kk = 0; kk < 2; kk++) {
        int kb = kk * 16 + tq * 2;
        float2 f00 = vA ? *(const float2*)&hp[(size_t)nodeA * 32 + kb]
                        : make_float2(0.f, 0.f);
        float2 f01 = vA ? *(const float2*)&hp[(size_t)nodeA * 32 + kb + 8]
                        : make_float2(0.f, 0.f);
        float2 f10 = vB ? *(const float2*)&hp[(size_t)nodeB * 32 + kb]
                        : make_float2(0.f, 0.f);
        float2 f11 = vB ? *(const float2*)&hp[(size_t)nodeB * 32 + kb + 8]
                        : make_float2(0.f, 0.f);
        afrag[kk][0] = pack_h2(f00.x, f00.y);
        afrag[kk][1] = pack_h2(f10.x, f10.y);
        afrag[kk][2] = pack_h2(f01.x, f01.y);
        afrag[kk][3] = pack_h2(f11.x, f11.y);
    }

    // ---- phase 1: 6 chunks of 256 cols; warp covers 32 cols per chunk ----
#pragma unroll
    for (int by = 0; by < 6; by++) {
        float acc[4][4];
#pragma unroll
        for (int nt = 0; nt < 4; nt++)
#pragma unroll
            for (int c = 0; c < 4; c++) acc[nt][c] = 0.f;
#pragma unroll
        for (int kk = 0; kk < 2; kk++) {
#pragma unroll
            for (int nt = 0; nt < 4; nt++) {
                int j = by * 256 + wn * 32 + nt * 8 + g;
                u32 b0 = *(const u32*)&Wl[j * 32 + kk * 16 + tq * 2];
                u32 b1v = *(const u32*)&Wl[j * 32 + kk * 16 + tq * 2 + 8];
                asm("mma.sync.aligned.m16n8k16.row.col.f32.f16.f16.f32 "
                    "{%0,%1,%2,%3}, {%4,%5,%6,%7}, {%8,%9}, {%0,%1,%2,%3};"
                    : "+f"(acc[nt][0]), "+f"(acc[nt][1]),
                      "+f"(acc[nt][2]), "+f"(acc[nt][3])
                    : "r"(afrag[kk][0]), "r"(afrag[kk][1]),
                      "r"(afrag[kk][2]), "r"(afrag[kk][3]),
                      "r"(b0), "r"(b1v));
            }
        }
#pragma unroll
        for (int nt = 0; nt < 4; nt++) {
            int pl = by * 128 + wn * 16 + nt * 4 + tq;
            sG[(m0 + g) * SROW + pl]     = __floats2half2_rn(acc[nt][0], acc[nt][1]);
            sG[(m0 + 8 + g) * SROW + pl] = __floats2half2_rn(acc[nt][2], acc[nt][3]);
        }
    }
    __syncthreads();

    // ---- export roots (pairs 672..703) ----
#pragma unroll
    for (int it = 0; it < 2; it++) {
        int id = it * 512 + t;
        int node = id >> 5, o = id & 31;
        if (nblk + node < NN)
            g_roots[(size_t)(nblk + node) * 32 + o] = sG[node * SROW + 672 + o];
    }

    // ---- phase 2: edges (warp handles 2 nodes) ----
    int edge = lane >> 4, kk2 = (lane & 15) * 2;
    for (int nn = 0; nn < 2; nn++) {
        int node = warp + nn * 16;
        int n = nblk + node;
        if (n >= NN) break;
        const __half2* gnode = &sG[node * SROW];
        __half2 G2[16];
#pragma unroll
        for (int k2 = 0; k2 < 16; k2++) G2[k2] = gnode[k2 * 32 + lane];
        float B = __low2float(gnode[640 + lane]);

        int beg = g_rowptr[n], end = beg + g_outdeg[n];
        int pos = beg;
        if (pos + 2 <= end) {
            int4 eA = g_erec[pos], eB = g_erec[pos + 1];
            while (true) {
                int np = pos + 2;
                bool more = np + 2 <= end;
                int4 nA, nB;
                if (more) { nA = g_erec[np]; nB = g_erec[np + 1]; }
                // on-the-fly hidden for my lane's k-pair (edge A or B)
                float dd = __int_as_float(edge ? eB.z : eA.z);
                int   rr = edge ? eB.x : eA.x;
                float h0 = fmaxf(fmaf(dd, sW1d[kk2],     sW1rb[rr][kk2]),     0.f);
                float h1 = fmaxf(fmaf(dd, sW1d[kk2 + 1], sW1rb[rr][kk2 + 1]), 0.f);
                u32 myh = pack_h2(h0, h1);

                __half2 z = __float2half2_rn(0.f);
                __half2 a0 = z, a1 = z, b0 = z, b1v = z;
#pragma unroll
                for (int k2 = 0; k2 < 16; k2 += 2) {
                    u32 ha0 = __shfl_sync(0xffffffffu, myh, k2);
                    u32 ha1 = __shfl_sync(0xffffffffu, myh, k2 + 1);
                    u32 hb0 = __shfl_sync(0xffffffffu, myh, 16 + k2);
                    u32 hb1 = __shfl_sync(0xffffffffu, myh, 16 + k2 + 1);
                    a0  = __hfma2(*(__half2*)&ha0, G2[k2],     a0);
                    a1  = __hfma2(*(__half2*)&ha1, G2[k2 + 1], a1);
                    b0  = __hfma2(*(__half2*)&hb0, G2[k2],     b0);
                    b1v = __hfma2(*(__half2*)&hb1, G2[k2 + 1], b1v);
                }
                float2 fA0 = __half22float2(a0), fA1 = __half22float2(a1);
                float2 fB0 = __half22float2(b0), fB1 = __half22float2(b1v);
                float mmA = (fA0.x + fA0.y) + (fA1.x + fA1.y) + B;
                float mmB = (fB0.x + fB0.y) + (fB1.x + fB1.y) + B;
                __half2 xpA = gnode[512 + (eA.x >> 1) * 32 + lane];
                __half2 xpB = gnode[512 + (eB.x >> 1) * 32 + lane];
                float xrA = (eA.x & 1) ? __high2float(xpA) : __low2float(xpA);
                float xrB = (eB.x & 1) ? __high2float(xpB) : __low2float(xpB);
                float dvA = xrA * __int_as_float(eA.y);
                float dvB = xrB * __int_as_float(eB.y);
                g_msg2[(size_t)pos * 32 + lane]       = pack_h2(mmA, dvA);
                g_msg2[(size_t)(pos + 1) * 32 + lane] = pack_h2(mmB, dvB);
                if (!more) break;
                pos = np; eA = nA; eB = nB;
            }
            pos += 2;
        }
        if (pos < end) {   // tail single edge
            int4 eA = g_erec[pos];
            float dd = __int_as_float(eA.z);
            int   rr = eA.x;
            float h0 = fmaxf(fmaf(dd, sW1d[kk2],     sW1rb[rr][kk2]),     0.f);
            float h1 = fmaxf(fmaf(dd, sW1d[kk2 + 1], sW1rb[rr][kk2 + 1]), 0.f);
            u32 myh = pack_h2(h0, h1);
            __half2 z = __float2half2_rn(0.f);
            __half2 a0 = z, a1 = z;
#pragma unroll
            for (int k2 = 0; k2 < 16; k2 += 2) {
                u32 ha0 = __shfl_sync(0xffffffffu, myh, k2);
                u32 ha1 = __shfl_sync(0xffffffffu, myh, k2 + 1);
                a0 = __hfma2(*(__half2*)&ha0, G2[k2],     a0);
                a1 = __hfma2(*(__half2*)&ha1, G2[k2 + 1], a1);
            }
            float2 fA0 = __half22float2(a0), fA1 = __half22float2(a1);
            float mmA = (fA0.x + fA0.y) + (fA1.x + fA1.y) + B;
            __half2 xpA = gnode[512 + (eA.x >> 1) * 32 + lane];
            float xrA = (eA.x & 1) ? __high2float(xpA) : __low2float(xpA);
            float dvA = xrA * __int_as_float(eA.y);
            g_msg2[(size_t)pos * 32 + lane] = pack_h2(mmA, dvA);
        }
    }
}

// ---------------- per-layer gather + combine (warp per destination) ---------
__global__ __launch_bounds__(256) void gather_kernel(
    int p, const float* __restrict__ rbias, const float* __restrict__ nbias,
    float* __restrict__ out_final) {
    int t = threadIdx.x, warp = t >> 5, lane = t & 31;
    int n = blockIdx.x * WPB + warp;
    if (n >= NN) return;

    int beg = g_inrow[n], cnt = g_indeg[n];
    float mms = 0.f, dvs = 0.f;
    int j = 0;
    for (; j + 4 <= cnt; j += 4) {
        int p0 = g_inlist[beg + j + 0];
        int p1 = g_inlist[beg + j + 1];
        int p2 = g_inlist[beg + j + 2];
        int p3 = g_inlist[beg + j + 3];
        u32 v0 = g_msg2[(size_t)p0 * 32 + lane];
        u32 v1 = g_msg2[(size_t)p1 * 32 + lane];
        u32 v2 = g_msg2[(size_t)p2 * 32 + lane];
        u32 v3 = g_msg2[(size_t)p3 * 32 + lane];
        float2 f0 = __half22float2(*(__half2*)&v0);
        float2 f1 = __half22float2(*(__half2*)&v1);
        float2 f2 = __half22float2(*(__half2*)&v2);
        float2 f3 = __half22float2(*(__half2*)&v3);
        mms += (f0.x + f1.x) + (f2.x + f3.x);
        dvs += (f0.y + f1.y) + (f2.y + f3.y);
    }
    for (; j < cnt; j++) {
        int pi = g_inlist[beg + j];
        u32 v = g_msg2[(size_t)pi * 32 + lane];
        float2 f = __half22float2(*(__half2*)&v);
        mms += f.x;
        dvs += f.y;
    }
    float invd = 1.f / fmaxf((float)cnt, 1.f);

    size_t idx = (size_t)n * 32 + lane;
    float2 roots = __half22float2(g_roots[idx]);
    float hv = g_h[p][idx];
    float v = hv + fmaxf(roots.x + rbias[lane] + dvs, 0.f)
                 + fmaxf(roots.y + nbias[lane] + mms * invd, 0.f);
    if (out_final) out_final[idx] = v;
    else           g_h[p ^ 1][idx] = v;
}

// ---------------- host launch ------------------------------------------------
extern "C" void kernel_launch(void* const* d_in, const int* in_sizes, int n_in,
                              void* d_out, int out_size) {
    const float* x     = (const float*)d_in[0];
    const int*   eidx  = (const int*)  d_in[1];   // [2,E]: src then dst
    const int*   etype = (const int*)  d_in[2];
    const float* edist = (const float*)d_in[3];
    const float* fcW   = (const float*)d_in[4];
    const float* fcb   = (const float*)d_in[5];
    const float* rW    = (const float*)d_in[6];   // [L,R,32,32]
    const float* rroot = (const float*)d_in[7];   // [L,32,32]
    const float* rbias = (const float*)d_in[8];   // [L,32]
    const float* W1    = (const float*)d_in[9];   // [9,32]
    const float* b1    = (const float*)d_in[10];  // [32]
    const float* W2    = (const float*)d_in[11];  // [32,1024]
    const float* b2    = (const float*)d_in[12];  // [1024]
    const float* nroot = (const float*)d_in[13];  // [L,32,32]
    const float* nbias = (const float*)d_in[14];  // [L,32]
    float* out = (float*)d_out;

    const int* srcp = eidx;
    const int* dstp = eidx + EE;

    int smem = 32 * SROW * 4;  // 98816 bytes
    cudaFuncSetAttribute(fusedmsg_kernel,
                         cudaFuncAttributeMaxDynamicSharedMemorySize, smem);

    init_kernel<<<(NN * NREL + 255) / 256, 256>>>();
    count_kernel<<<(EE + 255) / 256, 256>>>(srcp, dstp, etype);
    assign_kernel<<<(NN * NREL + 255) / 256, 256>>>();
    fill_kernel<<<(EE + 255) / 256, 256>>>(srcp, dstp, etype, edist);
    wcat_kernel<<<(NLAY * NCOL * 32 + 255) / 256, 256>>>(W2, rW, b2, rroot, nroot);
    fc_kernel<<<(NN + WPB - 1) / WPB, WPB * 32>>>(x, fcW, fcb);

    for (int l = 0; l < NLAY; l++) {
        int p = l & 1;
        fusedmsg_kernel<<<(NN + 31) / 32, 512, smem>>>(p, l, W1, b1);
        gather_kernel<<<(NN + WPB - 1) / WPB, WPB * 32>>>(
            p, rbias + (size_t)l * 32, nbias + (size_t)l * 32,
            (l == NLAY - 1) ? out : nullptr);
    }
}

// round 11
// speedup vs baseline: 3.6634x; 1.0112x over previous
#include <cuda_runtime.h>
#include <cuda_fp16.h>
#include <cstdint>

#define NN    50000
#define EE    400000
#define NREL  8
#define NLAY  5
#define WPB   8            // warps per block (gather)
#define NCOL  1536         // GEMM N: 1024 G | 256 Xr | 64 B | 64 roots | pad
#define SROW  772          // smem row stride in half2 (bank-conflict-free)

typedef unsigned int u32;

// ---------------- scratch (static device globals; no allocations) ----------
__device__ __half   g_WcatH[NLAY][NCOL * 32];    // fused fp16 weights, col-major [j][i]
__device__ __half2  g_roots[NN * 32];            // per-node (rroot,nroot) pairs
__device__ float    g_h[2][NN * 32];
__device__ float    g_invrel[NREL][NN];
__device__ int      g_counter[2];
__device__ int      g_outdeg[NN];
__device__ int      g_indeg[NN];
__device__ int      g_cursor[NN];
__device__ int      g_incur[NN];
__device__ int      g_rowptr[NN];
__device__ int      g_inrow[NN];
__device__ int4     g_erec[EE];                  // {r, wr_bits, dist_bits, dst_slot}
__device__ u32      g_msg2[(size_t)EE * 32];     // per-edge half2(mm, dv) in dst order

__device__ __forceinline__ u32 pack_h2(float a, float b) {
    __half2 h = __floats2half2_rn(a, b);
    return *(u32*)&h;
}

// ---------------- init / counts ----------------------------------------------
__global__ void init_kernel() {
    int i = blockIdx.x * blockDim.x + threadIdx.x;
    if (i < 2) g_counter[i] = 0;
    if (i < NN) { g_outdeg[i] = 0; g_indeg[i] = 0; }
    if (i < NN * NREL) ((float*)g_invrel)[i] = 0.f;
}

__global__ void count_kernel(const int* __restrict__ src,
                             const int* __restrict__ dst,
                             const int* __restrict__ etype) {
    int e = blockIdx.x * blockDim.x + threadIdx.x;
    if (e >= EE) return;
    int d = dst[e], r = etype[e];
    atomicAdd(&g_indeg[d], 1);
    atomicAdd(&g_invrel[r][d], 1.f);
    atomicAdd(&g_outdeg[src[e]], 1);
}

// invert rel counts + assign CSR segments (order-free)
__global__ void assign_kernel() {
    int i = blockIdx.x * blockDim.x + threadIdx.x;
    if (i < NN * NREL) {
        float v = ((float*)g_invrel)[i];
        ((float*)g_invrel)[i] = 1.f / fmaxf(v, 1.f);
    }
    if (i < NN) {
        g_rowptr[i] = atomicAdd(&g_counter[0], g_outdeg[i]);
        g_inrow[i]  = atomicAdd(&g_counter[1], g_indeg[i]);
        g_cursor[i] = 0;
        g_incur[i]  = 0;
    }
}

__global__ void fill_kernel(const int* __restrict__ src,
                            const int* __restrict__ dst,
                            const int* __restrict__ etype,
                            const float* __restrict__ edist) {
    int e = blockIdx.x * blockDim.x + threadIdx.x;
    if (e >= EE) return;
    int s = src[e], d = dst[e], r = etype[e];
    int pos = g_rowptr[s] + atomicAdd(&g_cursor[s], 1);
    int pin = g_inrow[d] + atomicAdd(&g_incur[d], 1);
    int4 rec;
    rec.x = r;
    rec.y = __float_as_int(g_invrel[r][d]);
    rec.z = __float_as_int(edist[e]);
    rec.w = pin;
    g_erec[pos] = rec;
}

// ---------------- build fused fp16 weight matrix, col-major [j][i] -----------
__global__ void wcat_kernel(const float* __restrict__ W2,
                            const float* __restrict__ rW,
                            const float* __restrict__ b2,
                            const float* __restrict__ rroot,
                            const float* __restrict__ nroot) {
    int idx = blockIdx.x * blockDim.x + threadIdx.x;
    if (idx >= NLAY * NCOL * 32) return;
    int l = idx / (NCOL * 32);
    int rem = idx % (NCOL * 32);
    int j = rem >> 5, i = rem & 31;
    int p = j >> 1, par = j & 1;
    float v = 0.f;
    if (p < 512) {
        int k = 2 * (p >> 5) + par, o = p & 31;
        v = W2[k * 1024 + i * 32 + o];
    } else if (p < 640) {
        int r = 2 * ((p - 512) >> 5) + par, o = p & 31;
        v = rW[(((size_t)l * NREL + r) * 32 + i) * 32 + o];
    } else if (p < 672) {
        if (par == 0) v = b2[i * 32 + (p - 640)];
    } else if (p < 704) {
        int o = p - 672;
        v = par ? nroot[((size_t)l * 32 + i) * 32 + o]
                : rroot[((size_t)l * 32 + i) * 32 + o];
    }
    g_WcatH[l][rem] = __float2half(v);
}

// ---------------- h0 = relu(x @ fc_W + fc_b) --------------------------------
__global__ __launch_bounds__(WPB * 32) void fc_kernel(
    const float* __restrict__ x, const float* __restrict__ W,
    const float* __restrict__ b) {
    int warp = threadIdx.x >> 5, lane = threadIdx.x & 31;
    int n = blockIdx.x * WPB + warp;
    if (n >= NN) return;
    float xv = x[n * 32 + lane];
    float acc = b[lane];
#pragma unroll
    for (int k = 0; k < 32; k++)
        acc = fmaf(__shfl_sync(0xffffffffu, xv, k), W[k * 32 + lane], acc);
    g_h[0][n * 32 + lane] = fmaxf(acc, 0.f);
}

// ---------------- fused GEMM(mma) + message kernel ---------------------------
// 512 threads, 32 nodes/block. Phase 1: 16 warps (2m x 8n) tensor GEMM -> smem.
// Phase 2: warp walks 2 nodes' CSR edges, hid computed on the fly; messages
// written directly to dst-ordered slots.
__global__ __launch_bounds__(512, 2) void fusedmsg_kernel(
    int p, int l, const float* __restrict__ W1, const float* __restrict__ b1) {
    extern __shared__ __half2 sG[];        // [32][SROW], 96.5 KB
    __shared__ float sW1d[32];             // W1[0][k]
    __shared__ float sW1rb[NREL][32];      // W1[1+r][k] + b1[k]
    int t = threadIdx.x, warp = t >> 5, lane = t & 31;
    int wm = warp >> 3, wn = warp & 7;
    int nblk = blockIdx.x * 32;
    int m0 = wm * 16;
    int g = lane >> 2, tq = lane & 3;
    const __half* Wl = g_WcatH[l];
    const float* hp = g_h[p];

    if (t < 32) sW1d[t] = W1[t];
    else if (t < 288) {
        int r = (t - 32) >> 5, k = t & 31;
        sW1rb[r][k] = W1[(1 + r) * 32 + k] + b1[k];
    }

    // ---- load A fragments once ----
    int nodeA = nblk + m0 + g;
    int nodeB = nodeA + 8;
    bool vA = nodeA < NN, vB = nodeB < NN;
    u32 afrag[2][4];
#pragma unroll
    for (int kk = 0; kk < 2; kk++) {
        int kb = kk * 16 + tq * 2;
        float2 f00 = vA ? *(const float2*)&hp[(size_t)nodeA * 32 + kb]
                        : make_float2(0.f, 0.f);
        float2 f01 = vA ? *(const float2*)&hp[(size_t)nodeA * 32 + kb + 8]
                        : make_float2(0.f, 0.f);
        float2 f10 = vB ? *(const float2*)&hp[(size_t)nodeB * 32 + kb]
                        : make_float2(0.f, 0.f);
        float2 f11 = vB ? *(const float2*)&hp[(size_t)nodeB * 32 + kb + 8]
                        : make_float2(0.f, 0.f);
        afrag[kk][0] = pack_h2(f00.x, f00.y);
        afrag[kk][1] = pack_h2(f10.x, f10.y);
        afrag[kk][2] = pack_h2(f01.x, f01.y);
        afrag[kk][3] = pack_h2(f11.x, f11.y);
    }

    // ---- phase 1: 6 chunks of 256 cols; warp covers 32 cols per chunk ----
#pragma unroll
    for (int by = 0; by < 6; by++) {
        float acc[4][4];
#pragma unroll
        for (int nt = 0; nt < 4; nt++)
#pragma unroll
            for (int c = 0; c < 4; c++) acc[nt][c] = 0.f;
#pragma unroll
        for (int kk = 0; kk < 2; kk++) {
#pragma unroll
            for (int nt = 0; nt < 4; nt++) {
                int j = by * 256 + wn * 32 + nt * 8 + g;
                u32 b0 = *(const u32*)&Wl[j * 32 + kk * 16 + tq * 2];
                u32 b1v = *(const u32*)&Wl[j * 32 + kk * 16 + tq * 2 + 8];
                asm("mma.sync.aligned.m16n8k16.row.col.f32.f16.f16.f32 "
                    "{%0,%1,%2,%3}, {%4,%5,%6,%7}, {%8,%9}, {%0,%1,%2,%3};"
                    : "+f"(acc[nt][0]), "+f"(acc[nt][1]),
                      "+f"(acc[nt][2]), "+f"(acc[nt][3])
                    : "r"(afrag[kk][0]), "r"(afrag[kk][1]),
                      "r"(afrag[kk][2]), "r"(afrag[kk][3]),
                      "r"(b0), "r"(b1v));
            }
        }
#pragma unroll
        for (int nt = 0; nt < 4; nt++) {
            int pl = by * 128 + wn * 16 + nt * 4 + tq;
            sG[(m0 + g) * SROW + pl]     = __floats2half2_rn(acc[nt][0], acc[nt][1]);
            sG[(m0 + 8 + g) * SROW + pl] = __floats2half2_rn(acc[nt][2], acc[nt][3]);
        }
    }
    __syncthreads();

    // ---- export roots (pairs 672..703) ----
#pragma unroll
    for (int it = 0; it < 2; it++) {
        int id = it * 512 + t;
        int node = id >> 5, o = id & 31;
        if (nblk + node < NN)
            g_roots[(size_t)(nblk + node) * 32 + o] = sG[node * SROW + 672 + o];
    }

    // ---- phase 2: edges (warp handles 2 nodes) ----
    int edge = lane >> 4, kk2 = (lane & 15) * 2;
    for (int nn = 0; nn < 2; nn++) {
        int node = warp + nn * 16;
        int n = nblk + node;
        if (n >= NN) break;
        const __half2* gnode = &sG[node * SROW];
        __half2 G2[16];
#pragma unroll
        for (int k2 = 0; k2 < 16; k2++) G2[k2] = gnode[k2 * 32 + lane];
        float B = __low2float(gnode[640 + lane]);

        int beg = g_rowptr[n], end = beg + g_outdeg[n];
        int pos = beg;
        if (pos + 2 <= end) {
            int4 eA = g_erec[pos], eB = g_erec[pos + 1];
            while (true) {
                int np = pos + 2;
                bool more = np + 2 <= end;
                int4 nA, nB;
                if (more) { nA = g_erec[np]; nB = g_erec[np + 1]; }
                // on-the-fly hidden for my lane's k-pair (edge A or B)
                float dd = __int_as_float(edge ? eB.z : eA.z);
                int   rr = edge ? eB.x : eA.x;
                float h0 = fmaxf(fmaf(dd, sW1d[kk2],     sW1rb[rr][kk2]),     0.f);
                float h1 = fmaxf(fmaf(dd, sW1d[kk2 + 1], sW1rb[rr][kk2 + 1]), 0.f);
                u32 myh = pack_h2(h0, h1);

                __half2 z = __float2half2_rn(0.f);
                __half2 a0 = z, a1 = z, b0 = z, b1v = z;
#pragma unroll
                for (int k2 = 0; k2 < 16; k2 += 2) {
                    u32 ha0 = __shfl_sync(0xffffffffu, myh, k2);
                    u32 ha1 = __shfl_sync(0xffffffffu, myh, k2 + 1);
                    u32 hb0 = __shfl_sync(0xffffffffu, myh, 16 + k2);
                    u32 hb1 = __shfl_sync(0xffffffffu, myh, 16 + k2 + 1);
                    a0  = __hfma2(*(__half2*)&ha0, G2[k2],     a0);
                    a1  = __hfma2(*(__half2*)&ha1, G2[k2 + 1], a1);
                    b0  = __hfma2(*(__half2*)&hb0, G2[k2],     b0);
                    b1v = __hfma2(*(__half2*)&hb1, G2[k2 + 1], b1v);
                }
                float2 fA0 = __half22float2(a0), fA1 = __half22float2(a1);
                float2 fB0 = __half22float2(b0), fB1 = __half22float2(b1v);
                float mmA = (fA0.x + fA0.y) + (fA1.x + fA1.y) + B;
                float mmB = (fB0.x + fB0.y) + (fB1.x + fB1.y) + B;
                __half2 xpA = gnode[512 + (eA.x >> 1) * 32 + lane];
                __half2 xpB = gnode[512 + (eB.x >> 1) * 32 + lane];
                float xrA = (eA.x & 1) ? __high2float(xpA) : __low2float(xpA);
                float xrB = (eB.x & 1) ? __high2float(xpB) : __low2float(xpB);
                float dvA = xrA * __int_as_float(eA.y);
                float dvB = xrB * __int_as_float(eB.y);
                g_msg2[(size_t)eA.w * 32 + lane] = pack_h2(mmA, dvA);
                g_msg2[(size_t)eB.w * 32 + lane] = pack_h2(mmB, dvB);
                if (!more) break;
                pos = np; eA = nA; eB = nB;
            }
            pos += 2;
        }
        if (pos < end) {   // tail single edge
            int4 eA = g_erec[pos];
            float dd = __int_as_float(eA.z);
            int   rr = eA.x;
            float h0 = fmaxf(fmaf(dd, sW1d[kk2],     sW1rb[rr][kk2]),     0.f);
            float h1 = fmaxf(fmaf(dd, sW1d[kk2 + 1], sW1rb[rr][kk2 + 1]), 0.f);
            u32 myh = pack_h2(h0, h1);
            __half2 z = __float2half2_rn(0.f);
            __half2 a0 = z, a1 = z;
#pragma unroll
            for (int k2 = 0; k2 < 16; k2 += 2) {
                u32 ha0 = __shfl_sync(0xffffffffu, myh, k2);
                u32 ha1 = __shfl_sync(0xffffffffu, myh, k2 + 1);
                a0 = __hfma2(*(__half2*)&ha0, G2[k2],     a0);
                a1 = __hfma2(*(__half2*)&ha1, G2[k2 + 1], a1);
            }
            float2 fA0 = __half22float2(a0), fA1 = __half22float2(a1);
            float mmA = (fA0.x + fA0.y) + (fA1.x + fA1.y) + B;
            __half2 xpA = gnode[512 + (eA.x >> 1) * 32 + lane];
            float xrA = (eA.x & 1) ? __high2float(xpA) : __low2float(xpA);
            float dvA = xrA * __int_as_float(eA.y);
            g_msg2[(size_t)eA.w * 32 + lane] = pack_h2(mmA, dvA);
        }
    }
}

// ---------------- per-layer gather + combine (warp per destination) ---------
// Messages are dst-ordered: node n owns msg2[inrow[n] .. inrow[n]+indeg[n]).
__global__ __launch_bounds__(256) void gather_kernel(
    int p, const float* __restrict__ rbias, const float* __restrict__ nbias,
    float* __restrict__ out_final) {
    int t = threadIdx.x, warp = t >> 5, lane = t & 31;
    int n = blockIdx.x * WPB + warp;
    if (n >= NN) return;

    int beg = g_inrow[n], cnt = g_indeg[n];
    const u32* base = &g_msg2[(size_t)beg * 32 + lane];
    float mms = 0.f, dvs = 0.f;
    int j = 0;
    for (; j + 8 <= cnt; j += 8) {
        u32 v0 = base[(j + 0) * 32];
        u32 v1 = base[(j + 1) * 32];
        u32 v2 = base[(j + 2) * 32];
        u32 v3 = base[(j + 3) * 32];
        u32 v4 = base[(j + 4) * 32];
        u32 v5 = base[(j + 5) * 32];
        u32 v6 = base[(j + 6) * 32];
        u32 v7 = base[(j + 7) * 32];
        float2 f0 = __half22float2(*(__half2*)&v0);
        float2 f1 = __half22float2(*(__half2*)&v1);
        float2 f2 = __half22float2(*(__half2*)&v2);
        float2 f3 = __half22float2(*(__half2*)&v3);
        float2 f4 = __half22float2(*(__half2*)&v4);
        float2 f5 = __half22float2(*(__half2*)&v5);
        float2 f6 = __half22float2(*(__half2*)&v6);
        float2 f7 = __half22float2(*(__half2*)&v7);
        mms += ((f0.x + f1.x) + (f2.x + f3.x)) + ((f4.x + f5.x) + (f6.x + f7.x));
        dvs += ((f0.y + f1.y) + (f2.y + f3.y)) + ((f4.y + f5.y) + (f6.y + f7.y));
    }
    for (; j < cnt; j++) {
        u32 v = base[j * 32];
        float2 f = __half22float2(*(__half2*)&v);
        mms += f.x;
        dvs += f.y;
    }
    float invd = 1.f / fmaxf((float)cnt, 1.f);

    size_t idx = (size_t)n * 32 + lane;
    float2 roots = __half22float2(g_roots[idx]);
    float hv = g_h[p][idx];
    float v = hv + fmaxf(roots.x + rbias[lane] + dvs, 0.f)
                 + fmaxf(roots.y + nbias[lane] + mms * invd, 0.f);
    if (out_final) out_final[idx] = v;
    else           g_h[p ^ 1][idx] = v;
}

// ---------------- host launch ------------------------------------------------
extern "C" void kernel_launch(void* const* d_in, const int* in_sizes, int n_in,
                              void* d_out, int out_size) {
    const float* x     = (const float*)d_in[0];
    const int*   eidx  = (const int*)  d_in[1];   // [2,E]: src then dst
    const int*   etype = (const int*)  d_in[2];
    const float* edist = (const float*)d_in[3];
    const float* fcW   = (const float*)d_in[4];
    const float* fcb   = (const float*)d_in[5];
    const float* rW    = (const float*)d_in[6];   // [L,R,32,32]
    const float* rroot = (const float*)d_in[7];   // [L,32,32]
    const float* rbias = (const float*)d_in[8];   // [L,32]
    const float* W1    = (const float*)d_in[9];   // [9,32]
    const float* b1    = (const float*)d_in[10];  // [32]
    const float* W2    = (const float*)d_in[11];  // [32,1024]
    const float* b2    = (const float*)d_in[12];  // [1024]
    const float* nroot = (const float*)d_in[13];  // [L,32,32]
    const float* nbias = (const float*)d_in[14];  // [L,32]
    float* out = (float*)d_out;

    const int* srcp = eidx;
    const int* dstp = eidx + EE;

    int smem = 32 * SROW * 4;  // 98816 bytes
    cudaFuncSetAttribute(fusedmsg_kernel,
                         cudaFuncAttributeMaxDynamicSharedMemorySize, smem);

    init_kernel<<<(NN * NREL + 255) / 256, 256>>>();
    count_kernel<<<(EE + 255) / 256, 256>>>(srcp, dstp, etype);
    assign_kernel<<<(NN * NREL + 255) / 256, 256>>>();
    fill_kernel<<<(EE + 255) / 256, 256>>>(srcp, dstp, etype, edist);
    wcat_kernel<<<(NLAY * NCOL * 32 + 255) / 256, 256>>>(W2, rW, b2, rroot, nroot);
    fc_kernel<<<(NN + WPB - 1) / WPB, WPB * 32>>>(x, fcW, fcb);

    for (int l = 0; l < NLAY; l++) {
        int p = l & 1;
        fusedmsg_kernel<<<(NN + 31) / 32, 512, smem>>>(p, l, W1, b1);
        gather_kernel<<<(NN + WPB - 1) / WPB, WPB * 32>>>(
            p, rbias + (size_t)l * 32, nbias + (size_t)l * 32,
            (l == NLAY - 1) ? out : nullptr);
    }
}

// round 12
// speedup vs baseline: 3.8902x; 1.0619x over previous
#include <cuda_runtime.h>
#include <cuda_fp16.h>
#include <cstdint>

#define NN    50000
#define EE    400000
#define NREL  8
#define NLAY  5
#define WPB   8            // warps per block (gather)
#define NCOL  1536         // GEMM N: 1024 G | 256 Xr | 64 B | 64 roots | pad
#define SROW  772          // smem row stride in half2 (bank-conflict-free)

typedef unsigned int u32;

// ---------------- scratch (static device globals; no allocations) ----------
__device__ __half   g_WcatH[NLAY][NCOL * 32];    // fused fp16 weights, col-major [j][i]
__device__ __half2  g_roots[NN * 32];            // per-node (rroot,nroot) pairs
__device__ float    g_h[2][NN * 32];
__device__ float    g_invrel[NREL][NN];
__device__ int      g_counter[2];
__device__ int      g_outdeg[NN];
__device__ int      g_indeg[NN];
__device__ int      g_cursor[NN];
__device__ int      g_incur[NN];
__device__ int      g_rowptr[NN];
__device__ int      g_inrow[NN];
__device__ int4     g_erec[EE];                  // {r, wr_bits, dist_bits, dst_slot}
__device__ u32      g_msg2[(size_t)EE * 32];     // per-edge half2(mm, dv) in dst order

__device__ __forceinline__ u32 pack_h2(float a, float b) {
    __half2 h = __floats2half2_rn(a, b);
    return *(u32*)&h;
}

// ---------------- init / counts ----------------------------------------------
__global__ void init_kernel() {
    int i = blockIdx.x * blockDim.x + threadIdx.x;
    if (i < 2) g_counter[i] = 0;
    if (i < NN) { g_outdeg[i] = 0; g_indeg[i] = 0; }
    if (i < NN * NREL) ((float*)g_invrel)[i] = 0.f;
}

__global__ void count_kernel(const int* __restrict__ src,
                             const int* __restrict__ dst,
                             const int* __restrict__ etype) {
    int e = blockIdx.x * blockDim.x + threadIdx.x;
    if (e >= EE) return;
    int d = dst[e], r = etype[e];
    atomicAdd(&g_indeg[d], 1);
    atomicAdd(&g_invrel[r][d], 1.f);
    atomicAdd(&g_outdeg[src[e]], 1);
}

// invert rel counts + assign CSR segments (order-free)
__global__ void assign_kernel() {
    int i = blockIdx.x * blockDim.x + threadIdx.x;
    if (i < NN * NREL) {
        float v = ((float*)g_invrel)[i];
        ((float*)g_invrel)[i] = 1.f / fmaxf(v, 1.f);
    }
    if (i < NN) {
        g_rowptr[i] = atomicAdd(&g_counter[0], g_outdeg[i]);
        g_inrow[i]  = atomicAdd(&g_counter[1], g_indeg[i]);
        g_cursor[i] = 0;
        g_incur[i]  = 0;
    }
}

__global__ void fill_kernel(const int* __restrict__ src,
                            const int* __restrict__ dst,
                            const int* __restrict__ etype,
                            const float* __restrict__ edist) {
    int e = blockIdx.x * blockDim.x + threadIdx.x;
    if (e >= EE) return;
    int s = src[e], d = dst[e], r = etype[e];
    int pos = g_rowptr[s] + atomicAdd(&g_cursor[s], 1);
    int pin = g_inrow[d] + atomicAdd(&g_incur[d], 1);
    int4 rec;
    rec.x = r;
    rec.y = __float_as_int(g_invrel[r][d]);
    rec.z = __float_as_int(edist[e]);
    rec.w = pin;
    g_erec[pos] = rec;
}

// ---------------- build fused fp16 weight matrix, col-major [j][i] -----------
__global__ void wcat_kernel(const float* __restrict__ W2,
                            const float* __restrict__ rW,
                            const float* __restrict__ b2,
                            const float* __restrict__ rroot,
                            const float* __restrict__ nroot) {
    int idx = blockIdx.x * blockDim.x + threadIdx.x;
    if (idx >= NLAY * NCOL * 32) return;
    int l = idx / (NCOL * 32);
    int rem = idx % (NCOL * 32);
    int j = rem >> 5, i = rem & 31;
    int p = j >> 1, par = j & 1;
    float v = 0.f;
    if (p < 512) {
        int k = 2 * (p >> 5) + par, o = p & 31;
        v = W2[k * 1024 + i * 32 + o];
    } else if (p < 640) {
        int r = 2 * ((p - 512) >> 5) + par, o = p & 31;
        v = rW[(((size_t)l * NREL + r) * 32 + i) * 32 + o];
    } else if (p < 672) {
        if (par == 0) v = b2[i * 32 + (p - 640)];
    } else if (p < 704) {
        int o = p - 672;
        v = par ? nroot[((size_t)l * 32 + i) * 32 + o]
                : rroot[((size_t)l * 32 + i) * 32 + o];
    }
    g_WcatH[l][rem] = __float2half(v);
}

// ---------------- h0 = relu(x @ fc_W + fc_b) --------------------------------
__global__ __launch_bounds__(WPB * 32) void fc_kernel(
    const float* __restrict__ x, const float* __restrict__ W,
    const float* __restrict__ b) {
    int warp = threadIdx.x >> 5, lane = threadIdx.x & 31;
    int n = blockIdx.x * WPB + warp;
    if (n >= NN) return;
    float xv = x[n * 32 + lane];
    float acc = b[lane];
#pragma unroll
    for (int k = 0; k < 32; k++)
        acc = fmaf(__shfl_sync(0xffffffffu, xv, k), W[k * 32 + lane], acc);
    g_h[0][n * 32 + lane] = fmaxf(acc, 0.f);
}

// ---------------- fused GEMM(mma) + message kernel ---------------------------
// 512 threads, 32 nodes/block.
// Phase 1: 16 warps each own 32 distinct cols per pass (3 passes), computing
//          BOTH m-tiles with one weight load (dedup).
// Phase 2: dynamic node queue; warp grabs nodes, G2 from smem, msgs dst-slotted.
__global__ __launch_bounds__(512, 2) void fusedmsg_kernel(
    int p, int l, const float* __restrict__ W1, const float* __restrict__ b1) {
    extern __shared__ __half2 sG[];        // [32][SROW], 96.5 KB
    __shared__ float sW1d[32];             // W1[0][k]
    __shared__ float sW1rb[NREL][32];      // W1[1+r][k] + b1[k]
    __shared__ int   sNext;
    int t = threadIdx.x, warp = t >> 5, lane = t & 31;
    int nblk = blockIdx.x * 32;
    int g = lane >> 2, tq = lane & 3;
    const __half* Wl = g_WcatH[l];
    const float* hp = g_h[p];

    if (t == 0) sNext = 0;
    if (t < 32) sW1d[t] = W1[t];
    else if (t >= 64 && t < 320) {
        int r = (t - 64) >> 5, k = t & 31;
        sW1rb[r][k] = W1[(1 + r) * 32 + k] + b1[k];
    }

    // ---- load A fragments for both m-tiles ----
    u32 afrag[2][2][4];
#pragma unroll
    for (int m = 0; m < 2; m++) {
        int nodeA = nblk + m * 16 + g;
        int nodeB = nodeA + 8;
        bool vA = nodeA < NN, vB = nodeB < NN;
#pragma unroll
        for (int kk = 0; kk < 2; kk++) {
            int kb = kk * 16 + tq * 2;
            float2 f00 = vA ? *(const float2*)&hp[(size_t)nodeA * 32 + kb]
                            : make_float2(0.f, 0.f);
            float2 f01 = vA ? *(const float2*)&hp[(size_t)nodeA * 32 + kb + 8]
                            : make_float2(0.f, 0.f);
            float2 f10 = vB ? *(const float2*)&hp[(size_t)nodeB * 32 + kb]
                            : make_float2(0.f, 0.f);
            float2 f11 = vB ? *(const float2*)&hp[(size_t)nodeB * 32 + kb + 8]
                            : make_float2(0.f, 0.f);
            afrag[m][kk][0] = pack_h2(f00.x, f00.y);
            afrag[m][kk][1] = pack_h2(f10.x, f10.y);
            afrag[m][kk][2] = pack_h2(f01.x, f01.y);
            afrag[m][kk][3] = pack_h2(f11.x, f11.y);
        }
    }

    // ---- phase 1: 3 passes of 512 cols; warp covers 32 distinct cols ----
#pragma unroll
    for (int by2 = 0; by2 < 3; by2++) {
        float acc[2][4][4];
#pragma unroll
        for (int m = 0; m < 2; m++)
#pragma unroll
            for (int nt = 0; nt < 4; nt++)
#pragma unroll
                for (int c = 0; c < 4; c++) acc[m][nt][c] = 0.f;
#pragma unroll
        for (int kk = 0; kk < 2; kk++) {
#pragma unroll
            for (int nt = 0; nt < 4; nt++) {
                int j = by2 * 512 + warp * 32 + nt * 8 + g;
                u32 b0 = *(const u32*)&Wl[j * 32 + kk * 16 + tq * 2];
                u32 b1v = *(const u32*)&Wl[j * 32 + kk * 16 + tq * 2 + 8];
#pragma unroll
                for (int m = 0; m < 2; m++) {
                    asm("mma.sync.aligned.m16n8k16.row.col.f32.f16.f16.f32 "
                        "{%0,%1,%2,%3}, {%4,%5,%6,%7}, {%8,%9}, {%0,%1,%2,%3};"
                        : "+f"(acc[m][nt][0]), "+f"(acc[m][nt][1]),
                          "+f"(acc[m][nt][2]), "+f"(acc[m][nt][3])
                        : "r"(afrag[m][kk][0]), "r"(afrag[m][kk][1]),
                          "r"(afrag[m][kk][2]), "r"(afrag[m][kk][3]),
                          "r"(b0), "r"(b1v));
                }
            }
        }
#pragma unroll
        for (int m = 0; m < 2; m++)
#pragma unroll
            for (int nt = 0; nt < 4; nt++) {
                int pl = by2 * 256 + warp * 16 + nt * 4 + tq;
                sG[(m * 16 + g) * SROW + pl] =
                    __floats2half2_rn(acc[m][nt][0], acc[m][nt][1]);
                sG[(m * 16 + 8 + g) * SROW + pl] =
                    __floats2half2_rn(acc[m][nt][2], acc[m][nt][3]);
            }
    }
    __syncthreads();

    // ---- export roots (pairs 672..703) ----
#pragma unroll
    for (int it = 0; it < 2; it++) {
        int id = it * 512 + t;
        int node = id >> 5, o = id & 31;
        if (nblk + node < NN)
            g_roots[(size_t)(nblk + node) * 32 + o] = sG[node * SROW + 672 + o];
    }

    // ---- phase 2: dynamic node queue ----
    int edge = lane >> 4, kk2 = (lane & 15) * 2;
    while (true) {
        int node = 0;
        if (lane == 0) node = atomicAdd(&sNext, 1);
        node = __shfl_sync(0xffffffffu, node, 0);
        if (node >= 32) break;
        int n = nblk + node;
        if (n >= NN) break;

        const __half2* gnode = &sG[node * SROW];
        __half2 G2[16];
#pragma unroll
        for (int k2 = 0; k2 < 16; k2++) G2[k2] = gnode[k2 * 32 + lane];
        float B = __low2float(gnode[640 + lane]);

        int beg = g_rowptr[n], end = beg + g_outdeg[n];
        int pos = beg;
        if (pos + 2 <= end) {
            int4 eA = g_erec[pos], eB = g_erec[pos + 1];
            while (true) {
                int np = pos + 2;
                bool more = np + 2 <= end;
                int4 nA, nB;
                if (more) { nA = g_erec[np]; nB = g_erec[np + 1]; }
                float dd = __int_as_float(edge ? eB.z : eA.z);
                int   rr = edge ? eB.x : eA.x;
                float h0 = fmaxf(fmaf(dd, sW1d[kk2],     sW1rb[rr][kk2]),     0.f);
                float h1 = fmaxf(fmaf(dd, sW1d[kk2 + 1], sW1rb[rr][kk2 + 1]), 0.f);
                u32 myh = pack_h2(h0, h1);

                __half2 z = __float2half2_rn(0.f);
                __half2 a0 = z, a1 = z, b0 = z, b1v = z;
#pragma unroll
                for (int k2 = 0; k2 < 16; k2 += 2) {
                    u32 ha0 = __shfl_sync(0xffffffffu, myh, k2);
                    u32 ha1 = __shfl_sync(0xffffffffu, myh, k2 + 1);
                    u32 hb0 = __shfl_sync(0xffffffffu, myh, 16 + k2);
                    u32 hb1 = __shfl_sync(0xffffffffu, myh, 16 + k2 + 1);
                    a0  = __hfma2(*(__half2*)&ha0, G2[k2],     a0);
                    a1  = __hfma2(*(__half2*)&ha1, G2[k2 + 1], a1);
                    b0  = __hfma2(*(__half2*)&hb0, G2[k2],     b0);
                    b1v = __hfma2(*(__half2*)&hb1, G2[k2 + 1], b1v);
                }
                float2 fA0 = __half22float2(a0), fA1 = __half22float2(a1);
                float2 fB0 = __half22float2(b0), fB1 = __half22float2(b1v);
                float mmA = (fA0.x + fA0.y) + (fA1.x + fA1.y) + B;
                float mmB = (fB0.x + fB0.y) + (fB1.x + fB1.y) + B;
                __half2 xpA = gnode[512 + (eA.x >> 1) * 32 + lane];
                __half2 xpB = gnode[512 + (eB.x >> 1) * 32 + lane];
                float xrA = (eA.x & 1) ? __high2float(xpA) : __low2float(xpA);
                float xrB = (eB.x & 1) ? __high2float(xpB) : __low2float(xpB);
                float dvA = xrA * __int_as_float(eA.y);
                float dvB = xrB * __int_as_float(eB.y);
                g_msg2[(size_t)eA.w * 32 + lane] = pack_h2(mmA, dvA);
                g_msg2[(size_t)eB.w * 32 + lane] = pack_h2(mmB, dvB);
                if (!more) break;
                pos = np; eA = nA; eB = nB;
            }
            pos += 2;
        }
        if (pos < end) {   // tail single edge
            int4 eA = g_erec[pos];
            float dd = __int_as_float(eA.z);
            int   rr = eA.x;
            float h0 = fmaxf(fmaf(dd, sW1d[kk2],     sW1rb[rr][kk2]),     0.f);
            float h1 = fmaxf(fmaf(dd, sW1d[kk2 + 1], sW1rb[rr][kk2 + 1]), 0.f);
            u32 myh = pack_h2(h0, h1);
            __half2 z = __float2half2_rn(0.f);
            __half2 a0 = z, a1 = z;
#pragma unroll
            for (int k2 = 0; k2 < 16; k2 += 2) {
                u32 ha0 = __shfl_sync(0xffffffffu, myh, k2);
                u32 ha1 = __shfl_sync(0xffffffffu, myh, k2 + 1);
                a0 = __hfma2(*(__half2*)&ha0, G2[k2],     a0);
                a1 = __hfma2(*(__half2*)&ha1, G2[k2 + 1], a1);
            }
            float2 fA0 = __half22float2(a0), fA1 = __half22float2(a1);
            float mmA = (fA0.x + fA0.y) + (fA1.x + fA1.y) + B;
            __half2 xpA = gnode[512 + (eA.x >> 1) * 32 + lane];
            float xrA = (eA.x & 1) ? __high2float(xpA) : __low2float(xpA);
            float dvA = xrA * __int_as_float(eA.y);
            g_msg2[(size_t)eA.w * 32 + lane] = pack_h2(mmA, dvA);
        }
    }
}

// ---------------- per-layer gather + combine (warp per destination) ---------
// Messages are dst-ordered: node n owns msg2[inrow[n] .. inrow[n]+indeg[n]).
__global__ __launch_bounds__(256) void gather_kernel(
    int p, const float* __restrict__ rbias, const float* __restrict__ nbias,
    float* __restrict__ out_final) {
    int t = threadIdx.x, warp = t >> 5, lane = t & 31;
    int n = blockIdx.x * WPB + warp;
    if (n >= NN) return;

    int beg = g_inrow[n], cnt = g_indeg[n];
    const u32* base = &g_msg2[(size_t)beg * 32 + lane];
    float mms = 0.f, dvs = 0.f;
    int j = 0;
    for (; j + 8 <= cnt; j += 8) {
        u32 v0 = base[(j + 0) * 32];
        u32 v1 = base[(j + 1) * 32];
        u32 v2 = base[(j + 2) * 32];
        u32 v3 = base[(j + 3) * 32];
        u32 v4 = base[(j + 4) * 32];
        u32 v5 = base[(j + 5) * 32];
        u32 v6 = base[(j + 6) * 32];
        u32 v7 = base[(j + 7) * 32];
        float2 f0 = __half22float2(*(__half2*)&v0);
        float2 f1 = __half22float2(*(__half2*)&v1);
        float2 f2 = __half22float2(*(__half2*)&v2);
        float2 f3 = __half22float2(*(__half2*)&v3);
        float2 f4 = __half22float2(*(__half2*)&v4);
        float2 f5 = __half22float2(*(__half2*)&v5);
        float2 f6 = __half22float2(*(__half2*)&v6);
        float2 f7 = __half22float2(*(__half2*)&v7);
        mms += ((f0.x + f1.x) + (f2.x + f3.x)) + ((f4.x + f5.x) + (f6.x + f7.x));
        dvs += ((f0.y + f1.y) + (f2.y + f3.y)) + ((f4.y + f5.y) + (f6.y + f7.y));
    }
    for (; j < cnt; j++) {
        u32 v = base[j * 32];
        float2 f = __half22float2(*(__half2*)&v);
        mms += f.x;
        dvs += f.y;
    }
    float invd = 1.f / fmaxf((float)cnt, 1.f);

    size_t idx = (size_t)n * 32 + lane;
    float2 roots = __half22float2(g_roots[idx]);
    float hv = g_h[p][idx];
    float v = hv + fmaxf(roots.x + rbias[lane] + dvs, 0.f)
                 + fmaxf(roots.y + nbias[lane] + mms * invd, 0.f);
    if (out_final) out_final[idx] = v;
    else           g_h[p ^ 1][idx] = v;
}

// ---------------- host launch ------------------------------------------------
extern "C" void kernel_launch(void* const* d_in, const int* in_sizes, int n_in,
                              void* d_out, int out_size) {
    const float* x     = (const float*)d_in[0];
    const int*   eidx  = (const int*)  d_in[1];   // [2,E]: src then dst
    const int*   etype = (const int*)  d_in[2];
    const float* edist = (const float*)d_in[3];
    const float* fcW   = (const float*)d_in[4];
    const float* fcb   = (const float*)d_in[5];
    const float* rW    = (const float*)d_in[6];   // [L,R,32,32]
    const float* rroot = (const float*)d_in[7];   // [L,32,32]
    const float* rbias = (const float*)d_in[8];   // [L,32]
    const float* W1    = (const float*)d_in[9];   // [9,32]
    const float* b1    = (const float*)d_in[10];  // [32]
    const float* W2    = (const float*)d_in[11];  // [32,1024]
    const float* b2    = (const float*)d_in[12];  // [1024]
    const float* nroot = (const float*)d_in[13];  // [L,32,32]
    const float* nbias = (const float*)d_in[14];  // [L,32]
    float* out = (float*)d_out;

    const int* srcp = eidx;
    const int* dstp = eidx + EE;

    int smem = 32 * SROW * 4;  // 98816 bytes
    cudaFuncSetAttribute(fusedmsg_kernel,
                         cudaFuncAttributeMaxDynamicSharedMemorySize, smem);

    init_kernel<<<(NN * NREL + 255) / 256, 256>>>();
    count_kernel<<<(EE + 255) / 256, 256>>>(srcp, dstp, etype);
    assign_kernel<<<(NN * NREL + 255) / 256, 256>>>();
    fill_kernel<<<(EE + 255) / 256, 256>>>(srcp, dstp, etype, edist);
    wcat_kernel<<<(NLAY * NCOL * 32 + 255) / 256, 256>>>(W2, rW, b2, rroot, nroot);
    fc_kernel<<<(NN + WPB - 1) / WPB, WPB * 32>>>(x, fcW, fcb);

    for (int l = 0; l < NLAY; l++) {
        int p = l & 1;
        fusedmsg_kernel<<<(NN + 31) / 32, 512, smem>>>(p, l, W1, b1);
        gather_kernel<<<(NN + WPB - 1) / WPB, WPB * 32>>>(
            p, rbias + (size_t)l * 32, nbias + (size_t)l * 32,
            (l == NLAY - 1) ? out : nullptr);
    }
}